// round 2
// baseline (speedup 1.0000x reference)
#include <cuda_runtime.h>
#include <cuda_bf16.h>
#include <math.h>

// Problem constants (fixed by setup_inputs)
#define BATCH   32
#define DIM     4096
#define NH      32
#define NKV     8
#define HD      128
#define MAXS    2048
#define START_T 2047
#define T_TOT   2048   // START_T + 1
#define NREP    4      // NH / NKV
#define RSQRT_HD 0.088388347648318447f  // 1/sqrt(128)

// -------- device scratch (no allocations allowed) --------
__device__ float g_q[BATCH * NH * HD];     // 32*4096
__device__ float g_k[BATCH * NKV * HD];    // 32*1024
__device__ float g_v[BATCH * NKV * HD];    // 32*1024
__device__ float g_attn[BATCH * NH * HD];  // 32*4096

// -------- packed f32x2 helpers --------
__device__ __forceinline__ void ffma2(unsigned long long &acc,
                                      unsigned long long a,
                                      unsigned long long b) {
    asm("fma.rn.f32x2 %0, %1, %2, %0;" : "+l"(acc) : "l"(a), "l"(b));
}
__device__ __forceinline__ unsigned long long pack2(float w) {
    unsigned long long r;
    unsigned u = __float_as_uint(w);
    asm("mov.b64 %0, {%1, %1};" : "=l"(r) : "r"(u));
    return r;
}

// -------- zero scratch + output (atomics accumulate into them) --------
__global__ void zero_kernel(float *__restrict__ out) {
    int i = blockIdx.x * 256 + threadIdx.x;
    for (; i < 327680; i += 81920) {
        if (i < 131072)       g_q[i] = 0.f;
        else if (i < 163840)  g_k[i - 131072] = 0.f;
        else if (i < 196608)  g_v[i - 163840] = 0.f;
        else                  out[i - 196608] = 0.f;
    }
}

// -------- GEMM: Y[32,N] (+)= X[32,4096] @ W[4096,N] --------
// grid.x = N/256 column blocks, grid.y = K-split (KB = 4096/gridDim.y, multiple of 128)
// xsel: 0 -> Xext, 1 -> g_attn ; ysel: 0 g_q, 1 g_k, 2 g_v, 3 Yext
__global__ void __launch_bounds__(256)
gemm32_kernel(const float *__restrict__ Xext, const float *__restrict__ W,
              int xsel, int ysel, float *__restrict__ Yext, int N) {
    const float *X = xsel ? g_attn : Xext;
    float *Y = (ysel == 0) ? g_q : (ysel == 1) ? g_k : (ysel == 2) ? g_v : Yext;

    const int tid = threadIdx.x;
    const int j = blockIdx.x * 256 + tid;
    const int KB = DIM / gridDim.y;
    const int kbeg = blockIdx.y * KB;

    __shared__ float xs[128][32];   // [kk][batch]

    unsigned long long acc[16];
#pragma unroll
    for (int p = 0; p < 16; p++) acc[p] = 0ULL;

    const int bb = tid >> 3;   // batch row this thread loads (0..31)
    const int kg = tid & 7;    // k-group (16 elems each)

    for (int k0 = kbeg; k0 < kbeg + KB; k0 += 128) {
        const float *xrow = X + (size_t)bb * DIM + k0 + kg * 16;
        float4 xa = *(const float4 *)(xrow);
        float4 xb = *(const float4 *)(xrow + 4);
        float4 xc = *(const float4 *)(xrow + 8);
        float4 xd = *(const float4 *)(xrow + 12);
        int kb = kg * 16;
        xs[kb + 0][bb] = xa.x;  xs[kb + 1][bb] = xa.y;
        xs[kb + 2][bb] = xa.z;  xs[kb + 3][bb] = xa.w;
        xs[kb + 4][bb] = xb.x;  xs[kb + 5][bb] = xb.y;
        xs[kb + 6][bb] = xb.z;  xs[kb + 7][bb] = xb.w;
        xs[kb + 8][bb] = xc.x;  xs[kb + 9][bb] = xc.y;
        xs[kb + 10][bb] = xc.z; xs[kb + 11][bb] = xc.w;
        xs[kb + 12][bb] = xd.x; xs[kb + 13][bb] = xd.y;
        xs[kb + 14][bb] = xd.z; xs[kb + 15][bb] = xd.w;
        __syncthreads();

        const float *wp = W + (size_t)k0 * N + j;
#pragma unroll 4
        for (int kk = 0; kk < 128; kk++) {
            unsigned long long wpk = pack2(wp[(size_t)kk * N]);
            const unsigned long long *xr2 = (const unsigned long long *)&xs[kk][0];
#pragma unroll
            for (int p = 0; p < 16; p++) ffma2(acc[p], xr2[p], wpk);
        }
        __syncthreads();
    }

#pragma unroll
    for (int p = 0; p < 16; p++) {
        unsigned lo, hi;
        asm("mov.b64 {%0,%1}, %2;" : "=r"(lo), "=r"(hi) : "l"(acc[p]));
        atomicAdd(&Y[(size_t)(2 * p) * N + j], __uint_as_float(lo));
        atomicAdd(&Y[(size_t)(2 * p + 1) * N + j], __uint_as_float(hi));
    }
}

// -------- RoPE on g_q (32 heads) and g_k (8 heads), pos = START_T --------
__global__ void rope_kernel(const float *__restrict__ fcos,
                            const float *__restrict__ fsin) {
    int idx = blockIdx.x * 256 + threadIdx.x;     // 32*40*64 = 81920 pairs
    int i = idx & 63;
    int head = (idx >> 6) % 40;
    int b = idx / (40 * 64);
    float c = fcos[i], s = fsin[i];
    float *base = (head < 32) ? (g_q + (size_t)b * 4096 + head * 128)
                              : (g_k + (size_t)b * 1024 + (head - 32) * 128);
    float xr = base[2 * i], xi = base[2 * i + 1];
    base[2 * i]     = xr * c - xi * s;
    base[2 * i + 1] = xr * s + xi * c;
}

// -------- Attention: one block per (b, kv_head); 4 query heads per block --------
__global__ void __launch_bounds__(256)
attn_kernel(const float *__restrict__ kc, const float *__restrict__ vc) {
    const int b = blockIdx.x >> 3;
    const int kv = blockIdx.x & 7;
    const int tid = threadIdx.x;
    const int lane = tid & 31;
    const int wid = tid >> 5;

    __shared__ float qs[512];
    __shared__ float sc[4 * T_TOT];   // scores -> probs
    __shared__ float accs[512];
    __shared__ float red[32];
    __shared__ float gmax[4], gsum[4];

    // load q heads kv*4 .. kv*4+3, pre-scaled
    for (int i = tid; i < 512; i += 256)
        qs[i] = g_q[(size_t)b * 4096 + kv * 512 + i] * RSQRT_HD;
    __syncthreads();

    float4 q0 = *(const float4 *)&qs[0 * 128 + 4 * lane];
    float4 q1 = *(const float4 *)&qs[1 * 128 + 4 * lane];
    float4 q2 = *(const float4 *)&qs[2 * 128 + 4 * lane];
    float4 q3 = *(const float4 *)&qs[3 * 128 + 4 * lane];

    const float *kbase = kc + ((size_t)b * MAXS * NKV + kv) * HD;
    const float *knew  = g_k + (size_t)(b * NKV + kv) * HD;

    // Phase 1: scores
    for (int t = wid; t < T_TOT; t += 8) {
        const float *kp = (t == START_T) ? knew : (kbase + (size_t)t * (NKV * HD));
        float4 k4 = *(const float4 *)(kp + 4 * lane);
        float s0 = k4.x * q0.x + k4.y * q0.y + k4.z * q0.z + k4.w * q0.w;
        float s1 = k4.x * q1.x + k4.y * q1.y + k4.z * q1.z + k4.w * q1.w;
        float s2 = k4.x * q2.x + k4.y * q2.y + k4.z * q2.z + k4.w * q2.w;
        float s3 = k4.x * q3.x + k4.y * q3.y + k4.z * q3.z + k4.w * q3.w;
#pragma unroll
        for (int off = 16; off; off >>= 1) {
            s0 += __shfl_xor_sync(~0u, s0, off);
            s1 += __shfl_xor_sync(~0u, s1, off);
            s2 += __shfl_xor_sync(~0u, s2, off);
            s3 += __shfl_xor_sync(~0u, s3, off);
        }
        if (lane == 0) {
            sc[t] = s0; sc[T_TOT + t] = s1; sc[2 * T_TOT + t] = s2; sc[3 * T_TOT + t] = s3;
        }
    }
    __syncthreads();

    // Phase 2: softmax (deferred normalization)
    float m0 = -1e30f, m1 = -1e30f, m2 = -1e30f, m3 = -1e30f;
    for (int t = tid; t < T_TOT; t += 256) {
        m0 = fmaxf(m0, sc[t]);
        m1 = fmaxf(m1, sc[T_TOT + t]);
        m2 = fmaxf(m2, sc[2 * T_TOT + t]);
        m3 = fmaxf(m3, sc[3 * T_TOT + t]);
    }
#pragma unroll
    for (int off = 16; off; off >>= 1) {
        m0 = fmaxf(m0, __shfl_xor_sync(~0u, m0, off));
        m1 = fmaxf(m1, __shfl_xor_sync(~0u, m1, off));
        m2 = fmaxf(m2, __shfl_xor_sync(~0u, m2, off));
        m3 = fmaxf(m3, __shfl_xor_sync(~0u, m3, off));
    }
    if (lane == 0) { red[wid * 4 + 0] = m0; red[wid * 4 + 1] = m1;
                     red[wid * 4 + 2] = m2; red[wid * 4 + 3] = m3; }
    __syncthreads();
    if (tid < 4) {
        float m = red[tid];
#pragma unroll
        for (int w = 1; w < 8; w++) m = fmaxf(m, red[w * 4 + tid]);
        gmax[tid] = m;
    }
    __syncthreads();
    m0 = gmax[0]; m1 = gmax[1]; m2 = gmax[2]; m3 = gmax[3];

    float sm0 = 0.f, sm1 = 0.f, sm2 = 0.f, sm3 = 0.f;
    for (int t = tid; t < T_TOT; t += 256) {
        float e0 = __expf(sc[t] - m0);           sc[t] = e0;           sm0 += e0;
        float e1 = __expf(sc[T_TOT + t] - m1);   sc[T_TOT + t] = e1;   sm1 += e1;
        float e2 = __expf(sc[2*T_TOT + t] - m2); sc[2*T_TOT + t] = e2; sm2 += e2;
        float e3 = __expf(sc[3*T_TOT + t] - m3); sc[3*T_TOT + t] = e3; sm3 += e3;
    }
#pragma unroll
    for (int off = 16; off; off >>= 1) {
        sm0 += __shfl_xor_sync(~0u, sm0, off);
        sm1 += __shfl_xor_sync(~0u, sm1, off);
        sm2 += __shfl_xor_sync(~0u, sm2, off);
        sm3 += __shfl_xor_sync(~0u, sm3, off);
    }
    __syncthreads();   // red reuse
    if (lane == 0) { red[wid * 4 + 0] = sm0; red[wid * 4 + 1] = sm1;
                     red[wid * 4 + 2] = sm2; red[wid * 4 + 3] = sm3; }
    __syncthreads();
    if (tid < 4) {
        float s = 0.f;
#pragma unroll
        for (int w = 0; w < 8; w++) s += red[w * 4 + tid];
        gsum[tid] = 1.0f / s;
    }

    // Phase 3: P @ V
    for (int i = tid; i < 512; i += 256) accs[i] = 0.f;
    __syncthreads();

    const float *vbase = vc + ((size_t)b * MAXS * NKV + kv) * HD;
    const float *vnew  = g_v + (size_t)(b * NKV + kv) * HD;
    float4 a0 = {0, 0, 0, 0}, a1 = {0, 0, 0, 0}, a2 = {0, 0, 0, 0}, a3 = {0, 0, 0, 0};
    for (int t = wid; t < T_TOT; t += 8) {
        const float *vp = (t == START_T) ? vnew : (vbase + (size_t)t * (NKV * HD));
        float4 v4 = *(const float4 *)(vp + 4 * lane);
        float p0 = sc[t], p1 = sc[T_TOT + t], p2 = sc[2 * T_TOT + t], p3 = sc[3 * T_TOT + t];
        a0.x += v4.x * p0; a0.y += v4.y * p0; a0.z += v4.z * p0; a0.w += v4.w * p0;
        a1.x += v4.x * p1; a1.y += v4.y * p1; a1.z += v4.z * p1; a1.w += v4.w * p1;
        a2.x += v4.x * p2; a2.y += v4.y * p2; a2.z += v4.z * p2; a2.w += v4.w * p2;
        a3.x += v4.x * p3; a3.y += v4.y * p3; a3.z += v4.z * p3; a3.w += v4.w * p3;
    }
    atomicAdd(&accs[0 * 128 + 4 * lane + 0], a0.x);
    atomicAdd(&accs[0 * 128 + 4 * lane + 1], a0.y);
    atomicAdd(&accs[0 * 128 + 4 * lane + 2], a0.z);
    atomicAdd(&accs[0 * 128 + 4 * lane + 3], a0.w);
    atomicAdd(&accs[1 * 128 + 4 * lane + 0], a1.x);
    atomicAdd(&accs[1 * 128 + 4 * lane + 1], a1.y);
    atomicAdd(&accs[1 * 128 + 4 * lane + 2], a1.z);
    atomicAdd(&accs[1 * 128 + 4 * lane + 3], a1.w);
    atomicAdd(&accs[2 * 128 + 4 * lane + 0], a2.x);
    atomicAdd(&accs[2 * 128 + 4 * lane + 1], a2.y);
    atomicAdd(&accs[2 * 128 + 4 * lane + 2], a2.z);
    atomicAdd(&accs[2 * 128 + 4 * lane + 3], a2.w);
    atomicAdd(&accs[3 * 128 + 4 * lane + 0], a3.x);
    atomicAdd(&accs[3 * 128 + 4 * lane + 1], a3.y);
    atomicAdd(&accs[3 * 128 + 4 * lane + 2], a3.z);
    atomicAdd(&accs[3 * 128 + 4 * lane + 3], a3.w);
    __syncthreads();

    for (int i = tid; i < 512; i += 256) {
        int h = i >> 7, d = i & 127;
        g_attn[(size_t)b * 4096 + (kv * NREP + h) * 128 + d] = accs[i] * gsum[h];
    }
}

extern "C" void kernel_launch(void *const *d_in, const int *in_sizes, int n_in,
                              void *d_out, int out_size) {
    const float *x    = (const float *)d_in[0];
    const float *wq   = (const float *)d_in[1];
    const float *wk   = (const float *)d_in[2];
    const float *wv   = (const float *)d_in[3];
    const float *wo   = (const float *)d_in[4];
    const float *kc   = (const float *)d_in[5];
    const float *vc   = (const float *)d_in[6];
    const float *fcos = (const float *)d_in[7];
    const float *fsin = (const float *)d_in[8];
    float *out = (float *)d_out;

    zero_kernel<<<320, 256>>>(out);

    // QKV projections
    gemm32_kernel<<<dim3(16, 16), 256>>>(x, wq, 0, 0, nullptr, 4096);
    gemm32_kernel<<<dim3(4, 32), 256>>>(x, wk, 0, 1, nullptr, 1024);
    gemm32_kernel<<<dim3(4, 32), 256>>>(x, wv, 0, 2, nullptr, 1024);

    rope_kernel<<<320, 256>>>(fcos, fsin);

    attn_kernel<<<BATCH * NKV, 256>>>(kc, vc);

    // Output projection into d_out
    gemm32_kernel<<<dim3(16, 16), 256>>>(nullptr, wo, 1, 3, out, 4096);
}

// round 4
// speedup vs baseline: 1.1893x; 1.1893x over previous
#include <cuda_runtime.h>
#include <math.h>

typedef unsigned long long ull;

#define BATCH   32
#define DIM     4096
#define NH      32
#define NKV     8
#define HD      128
#define MAXS    2048
#define START_T 2047
#define T_TOT   2048
#define RSQRT_HD 0.088388347648318447f

// -------- device scratch --------
__device__ float g_q[BATCH * NH * HD];
__device__ float g_k[BATCH * NKV * HD];
__device__ float g_v[BATCH * NKV * HD];
__device__ float g_attn[BATCH * NH * HD];

// -------- packed f32x2 helpers --------
__device__ __forceinline__ void ffma2(ull &acc, ull a, ull b) {
    asm("fma.rn.f32x2 %0, %1, %2, %0;" : "+l"(acc) : "l"(a), "l"(b));
}
__device__ __forceinline__ ull pack2(float w) {
    ull r; unsigned u = __float_as_uint(w);
    asm("mov.b64 %0, {%1, %1};" : "=l"(r) : "r"(u));
    return r;
}

// -------- zero scratch + output --------
__global__ void zero_kernel(float *__restrict__ out) {
    int i = blockIdx.x * 256 + threadIdx.x;
    for (; i < 327680; i += 81920) {
        if (i < 131072)       g_q[i] = 0.f;
        else if (i < 163840)  g_k[i - 131072] = 0.f;
        else if (i < 196608)  g_v[i - 163840] = 0.f;
        else                  out[i - 196608] = 0.f;
    }
}

// -------- GEMM body: Y[32,N] += X[32,4096] @ W[4096,N], K-split over grid.y --------
// Thread: 4 consecutive columns x 8 batches. acc = f32x2 over batch pairs.
__device__ __forceinline__ void gemm_body(const float *__restrict__ X,
                                          const float *__restrict__ W,
                                          float *__restrict__ Y, int N, int KB,
                                          float (*xs)[32]) {
    const int tid = threadIdx.x;
    const int tx = tid & 63;          // column group (4 cols)
    const int ty = tid >> 6;          // batch octet (8 batches)
    const int j0 = blockIdx.x * 256 + tx * 4;
    const int kbeg = blockIdx.y * KB;

    // stage x chunk transposed: xs[k][batch]
    const int nc = KB >> 2;
    for (int idx = tid; idx < 32 * nc; idx += 256) {
        int bb = idx / nc, c = idx % nc;
        float4 xv = *(const float4 *)(X + (size_t)bb * DIM + kbeg + 4 * c);
        xs[4 * c + 0][bb] = xv.x; xs[4 * c + 1][bb] = xv.y;
        xs[4 * c + 2][bb] = xv.z; xs[4 * c + 3][bb] = xv.w;
    }
    __syncthreads();

    ull acc[4][4];
#pragma unroll
    for (int c = 0; c < 4; c++)
#pragma unroll
        for (int i = 0; i < 4; i++) acc[c][i] = 0ULL;

    const float *wp = W + (size_t)kbeg * N + j0;
    for (int k = 0; k < KB; k += 4) {
        float4 w[4];
#pragma unroll
        for (int kk = 0; kk < 4; kk++)
            w[kk] = *(const float4 *)(wp + (size_t)(k + kk) * N);
#pragma unroll
        for (int kk = 0; kk < 4; kk++) {
            ull xp[4];
#pragma unroll
            for (int i = 0; i < 4; i++)
                xp[i] = *(const ull *)&xs[k + kk][ty * 8 + 2 * i];
            const float *wf = (const float *)&w[kk];
#pragma unroll
            for (int c = 0; c < 4; c++) {
                ull wc = pack2(wf[c]);
#pragma unroll
                for (int i = 0; i < 4; i++) ffma2(acc[c][i], xp[i], wc);
            }
        }
    }

#pragma unroll
    for (int c = 0; c < 4; c++)
#pragma unroll
        for (int i = 0; i < 4; i++) {
            float2 v = *(float2 *)&acc[c][i];
            int bb = ty * 8 + 2 * i;
            atomicAdd(&Y[(size_t)bb * N + j0 + c], v.x);
            atomicAdd(&Y[(size_t)(bb + 1) * N + j0 + c], v.y);
        }
}

__global__ void __launch_bounds__(256)
gemm_q_kernel(const float *__restrict__ X, const float *__restrict__ W) {
    __shared__ float xs[256][32];
    gemm_body(X, W, g_q, 4096, DIM / gridDim.y, xs);
}
__global__ void __launch_bounds__(256)
gemm_kv_kernel(const float *__restrict__ X, const float *__restrict__ Wk,
               const float *__restrict__ Wv) {
    __shared__ float xs[256][32];
    if (blockIdx.z == 0) gemm_body(X, Wk, g_k, 1024, DIM / gridDim.y, xs);
    else                 gemm_body(X, Wv, g_v, 1024, DIM / gridDim.y, xs);
}
__global__ void __launch_bounds__(256)
gemm_o_kernel(const float *__restrict__ W, float *__restrict__ out) {
    __shared__ float xs[256][32];
    gemm_body(g_attn, W, out, 4096, DIM / gridDim.y, xs);
}

// -------- RoPE --------
__global__ void rope_kernel(const float *__restrict__ fcos,
                            const float *__restrict__ fsin) {
    int idx = blockIdx.x * 256 + threadIdx.x;   // 32*40*64 pairs
    int i = idx & 63;
    int head = (idx >> 6) % 40;
    int bb = idx / (40 * 64);
    float c = fcos[i], s = fsin[i];
    float *base = (head < 32) ? (g_q + (size_t)bb * 4096 + head * 128)
                              : (g_k + (size_t)bb * 1024 + (head - 32) * 128);
    float xr = base[2 * i], xi = base[2 * i + 1];
    base[2 * i]     = xr * c - xi * s;
    base[2 * i + 1] = xr * s + xi * c;
}

// -------- Attention: block per (b, kv); half-warp owns one K/V row --------
__global__ void __launch_bounds__(256)
attn_kernel(const float *__restrict__ kc, const float *__restrict__ vc) {
    const int b = blockIdx.x >> 3;
    const int kv = blockIdx.x & 7;
    const int tid = threadIdx.x;
    const int lane = tid & 31;
    const int wid = tid >> 5;
    const int hl = lane & 15;     // position within half-warp
    const int half = lane >> 4;   // which row of the pair

    __shared__ float qs[512];
    __shared__ float sc[4 * T_TOT];
    __shared__ float accs[512];
    __shared__ float red[32];
    __shared__ float gmax[4], gsum[4];

    for (int i = tid; i < 512; i += 256) {
        qs[i] = g_q[(size_t)b * 4096 + kv * 512 + i] * RSQRT_HD;
        accs[i] = 0.f;
    }
    __syncthreads();

    // q packed: head h, lane slice d = hl*4 + {0..3} and hl*4+64 + {0..3}
    ull qp[4][4];
#pragma unroll
    for (int h = 0; h < 4; h++) {
        const ull *qa = (const ull *)&qs[h * 128 + hl * 4];
        const ull *qb = (const ull *)&qs[h * 128 + hl * 4 + 64];
        qp[h][0] = qa[0]; qp[h][1] = qa[1];
        qp[h][2] = qb[0]; qp[h][3] = qb[1];
    }

    const float *kbase = kc + ((size_t)b * MAXS * NKV + kv) * HD;
    const float *knew  = g_k + (size_t)(b * NKV + kv) * HD;

    // Phase 1: scores (4 rows per warp-iter, 4 LDG.128 in flight)
    for (int tb = wid * 4; tb < T_TOT; tb += 32) {
        int tA = tb + half, tB = tb + 2 + half;
        const float *kA = (tA == START_T) ? knew : kbase + (size_t)tA * (NKV * HD);
        const float *kB = (tB == START_T) ? knew : kbase + (size_t)tB * (NKV * HD);
        float4 a0 = *(const float4 *)(kA + hl * 4);
        float4 a1 = *(const float4 *)(kA + hl * 4 + 64);
        float4 c0 = *(const float4 *)(kB + hl * 4);
        float4 c1 = *(const float4 *)(kB + hl * 4 + 64);
        const ull *a0p = (const ull *)&a0, *a1p = (const ull *)&a1;
        const ull *c0p = (const ull *)&c0, *c1p = (const ull *)&c1;
        float fA[4], fB[4];
#pragma unroll
        for (int h = 0; h < 4; h++) {
            ull sA = 0ULL, sB = 0ULL;
            ffma2(sA, a0p[0], qp[h][0]); ffma2(sA, a0p[1], qp[h][1]);
            ffma2(sA, a1p[0], qp[h][2]); ffma2(sA, a1p[1], qp[h][3]);
            ffma2(sB, c0p[0], qp[h][0]); ffma2(sB, c0p[1], qp[h][1]);
            ffma2(sB, c1p[0], qp[h][2]); ffma2(sB, c1p[1], qp[h][3]);
            float2 va = *(float2 *)&sA, vb = *(float2 *)&sB;
            fA[h] = va.x + va.y; fB[h] = vb.x + vb.y;
        }
#pragma unroll
        for (int off = 8; off; off >>= 1)
#pragma unroll
            for (int h = 0; h < 4; h++) {
                fA[h] += __shfl_xor_sync(~0u, fA[h], off);
                fB[h] += __shfl_xor_sync(~0u, fB[h], off);
            }
        if (hl == 0) {
#pragma unroll
            for (int h = 0; h < 4; h++) {
                sc[h * T_TOT + tA] = fA[h];
                sc[h * T_TOT + tB] = fB[h];
            }
        }
    }
    __syncthreads();

    // Phase 2: softmax (deferred normalization)
    float m0 = -1e30f, m1 = -1e30f, m2 = -1e30f, m3 = -1e30f;
    for (int t = tid; t < T_TOT; t += 256) {
        m0 = fmaxf(m0, sc[t]);
        m1 = fmaxf(m1, sc[T_TOT + t]);
        m2 = fmaxf(m2, sc[2 * T_TOT + t]);
        m3 = fmaxf(m3, sc[3 * T_TOT + t]);
    }
#pragma unroll
    for (int off = 16; off; off >>= 1) {
        m0 = fmaxf(m0, __shfl_xor_sync(~0u, m0, off));
        m1 = fmaxf(m1, __shfl_xor_sync(~0u, m1, off));
        m2 = fmaxf(m2, __shfl_xor_sync(~0u, m2, off));
        m3 = fmaxf(m3, __shfl_xor_sync(~0u, m3, off));
    }
    if (lane == 0) { red[wid * 4 + 0] = m0; red[wid * 4 + 1] = m1;
                     red[wid * 4 + 2] = m2; red[wid * 4 + 3] = m3; }
    __syncthreads();
    if (tid < 4) {
        float m = red[tid];
#pragma unroll
        for (int w = 1; w < 8; w++) m = fmaxf(m, red[w * 4 + tid]);
        gmax[tid] = m;
    }
    __syncthreads();
    m0 = gmax[0]; m1 = gmax[1]; m2 = gmax[2]; m3 = gmax[3];

    float sm0 = 0.f, sm1 = 0.f, sm2 = 0.f, sm3 = 0.f;
    for (int t = tid; t < T_TOT; t += 256) {
        float e0 = __expf(sc[t] - m0);               sc[t] = e0;               sm0 += e0;
        float e1 = __expf(sc[T_TOT + t] - m1);       sc[T_TOT + t] = e1;       sm1 += e1;
        float e2 = __expf(sc[2 * T_TOT + t] - m2);   sc[2 * T_TOT + t] = e2;   sm2 += e2;
        float e3 = __expf(sc[3 * T_TOT + t] - m3);   sc[3 * T_TOT + t] = e3;   sm3 += e3;
    }
#pragma unroll
    for (int off = 16; off; off >>= 1) {
        sm0 += __shfl_xor_sync(~0u, sm0, off);
        sm1 += __shfl_xor_sync(~0u, sm1, off);
        sm2 += __shfl_xor_sync(~0u, sm2, off);
        sm3 += __shfl_xor_sync(~0u, sm3, off);
    }
    __syncthreads();
    if (lane == 0) { red[wid * 4 + 0] = sm0; red[wid * 4 + 1] = sm1;
                     red[wid * 4 + 2] = sm2; red[wid * 4 + 3] = sm3; }
    __syncthreads();
    if (tid < 4) {
        float s = 0.f;
#pragma unroll
        for (int w = 0; w < 8; w++) s += red[w * 4 + tid];
        gsum[tid] = 1.0f / s;
    }
    __syncthreads();

    // Phase 3: P @ V (same row-pair layout)
    ull oa[4][4];
#pragma unroll
    for (int h = 0; h < 4; h++)
#pragma unroll
        for (int j = 0; j < 4; j++) oa[h][j] = 0ULL;

    const float *vbase = vc + ((size_t)b * MAXS * NKV + kv) * HD;
    const float *vnew  = g_v + (size_t)(b * NKV + kv) * HD;
    for (int tb = wid * 4; tb < T_TOT; tb += 32) {
        int tA = tb + half, tB = tb + 2 + half;
        const float *vA = (tA == START_T) ? vnew : vbase + (size_t)tA * (NKV * HD);
        const float *vB = (tB == START_T) ? vnew : vbase + (size_t)tB * (NKV * HD);
        float4 a0 = *(const float4 *)(vA + hl * 4);
        float4 a1 = *(const float4 *)(vA + hl * 4 + 64);
        float4 c0 = *(const float4 *)(vB + hl * 4);
        float4 c1 = *(const float4 *)(vB + hl * 4 + 64);
        const ull *a0p = (const ull *)&a0, *a1p = (const ull *)&a1;
        const ull *c0p = (const ull *)&c0, *c1p = (const ull *)&c1;
#pragma unroll
        for (int h = 0; h < 4; h++) {
            ull pA = pack2(sc[h * T_TOT + tA]);
            ull pB = pack2(sc[h * T_TOT + tB]);
            ffma2(oa[h][0], a0p[0], pA); ffma2(oa[h][1], a0p[1], pA);
            ffma2(oa[h][2], a1p[0], pA); ffma2(oa[h][3], a1p[1], pA);
            ffma2(oa[h][0], c0p[0], pB); ffma2(oa[h][1], c0p[1], pB);
            ffma2(oa[h][2], c1p[0], pB); ffma2(oa[h][3], c1p[1], pB);
        }
    }

    // combine the two halves, then cross-warp accumulate in smem
#pragma unroll
    for (int h = 0; h < 4; h++)
#pragma unroll
        for (int j = 0; j < 4; j++) {
            float2 v = *(float2 *)&oa[h][j];
            v.x += __shfl_xor_sync(~0u, v.x, 16);
            v.y += __shfl_xor_sync(~0u, v.y, 16);
            if (half == 0) {
                int d = hl * 4 + (j & 1) * 2 + (j >> 1) * 64;
                atomicAdd(&accs[h * 128 + d], v.x);
                atomicAdd(&accs[h * 128 + d + 1], v.y);
            }
        }
    __syncthreads();

    for (int i = tid; i < 512; i += 256) {
        int h = i >> 7, d = i & 127;
        g_attn[(size_t)b * 4096 + (kv * 4 + h) * 128 + d] = accs[i] * gsum[h];
    }
}

extern "C" void kernel_launch(void *const *d_in, const int *in_sizes, int n_in,
                              void *d_out, int out_size) {
    const float *x    = (const float *)d_in[0];
    const float *wq   = (const float *)d_in[1];
    const float *wk   = (const float *)d_in[2];
    const float *wv   = (const float *)d_in[3];
    const float *wo   = (const float *)d_in[4];
    const float *kc   = (const float *)d_in[5];
    const float *vc   = (const float *)d_in[6];
    const float *fcos = (const float *)d_in[7];
    const float *fsin = (const float *)d_in[8];
    float *out = (float *)d_out;

    zero_kernel<<<320, 256>>>(out);

    gemm_q_kernel<<<dim3(16, 16), 256>>>(x, wq);          // KB=256, 256 CTAs
    gemm_kv_kernel<<<dim3(4, 32, 2), 256>>>(x, wk, wv);   // KB=128, 256 CTAs

    rope_kernel<<<320, 256>>>(fcos, fsin);

    attn_kernel<<<BATCH * NKV, 256>>>(kc, vc);

    gemm_o_kernel<<<dim3(16, 16), 256>>>(wo, out);        // KB=256, 256 CTAs
}

// round 5
// speedup vs baseline: 1.7309x; 1.4555x over previous
#include <cuda_runtime.h>
#include <math.h>

typedef unsigned long long ull;

#define BATCH   32
#define DIM     4096
#define NH      32
#define NKV     8
#define HD      128
#define MAXS    2048
#define START_T 2047
#define T_TOT   2048
#define RSQRT_HD 0.088388347648318447f

// -------- device scratch --------
__device__ float g_q[BATCH * NH * HD];
__device__ float g_k[BATCH * NKV * HD];
__device__ float g_v[BATCH * NKV * HD];
__device__ float g_attn[BATCH * NH * HD];

// -------- packed f32x2 helpers --------
__device__ __forceinline__ void ffma2(ull &acc, ull a, ull b) {
    asm("fma.rn.f32x2 %0, %1, %2, %0;" : "+l"(acc) : "l"(a), "l"(b));
}
__device__ __forceinline__ ull pack2(float w) {
    ull r; unsigned u = __float_as_uint(w);
    asm("mov.b64 %0, {%1, %1};" : "=l"(r) : "r"(u));
    return r;
}

// -------- zero scratch + output --------
__global__ void zero_kernel(float *__restrict__ out) {
    int i = blockIdx.x * 256 + threadIdx.x;
    for (; i < 327680; i += 81920) {
        if (i < 131072)       g_q[i] = 0.f;
        else if (i < 163840)  g_k[i - 131072] = 0.f;
        else if (i < 196608)  g_v[i - 163840] = 0.f;
        else                  out[i - 196608] = 0.f;
    }
}

// -------- GEMM body: Y[32,N] += X[32,4096] @ W[4096,N], K-split grid.y --------
// 512 threads: thread = 4 cols (tx*4) x 8 batches (ty*8). 8-deep W-load hoist.
__device__ __forceinline__ void gemm_body(const float *__restrict__ X,
                                          const float *__restrict__ W,
                                          float *__restrict__ Y, int N, int KB,
                                          float (*xs)[32]) {
    const int tid = threadIdx.x;
    const int tx = tid & 127;
    const int ty = tid >> 7;
    const int j0 = blockIdx.x * 512 + tx * 4;
    const int kbeg = blockIdx.y * KB;

    // stage x transposed: xs[k][batch]; bb = idx&31 -> conflict-free smem writes
    const int nc4 = KB >> 2;
    for (int idx = tid; idx < 32 * nc4; idx += 512) {
        int bb = idx & 31, c = idx >> 5;
        float4 xv = *(const float4 *)(X + (size_t)bb * DIM + kbeg + 4 * c);
        xs[4 * c + 0][bb] = xv.x; xs[4 * c + 1][bb] = xv.y;
        xs[4 * c + 2][bb] = xv.z; xs[4 * c + 3][bb] = xv.w;
    }
    __syncthreads();

    ull acc[4][4];
#pragma unroll
    for (int c = 0; c < 4; c++)
#pragma unroll
        for (int i = 0; i < 4; i++) acc[c][i] = 0ULL;

    const float *wp = W + (size_t)kbeg * N + j0;
    for (int k = 0; k < KB; k += 8) {
        const float *wk8 = wp + (size_t)k * N;
        float4 w[8];
#pragma unroll
        for (int kk = 0; kk < 8; kk++)
            w[kk] = *(const float4 *)(wk8 + (size_t)kk * N);
#pragma unroll
        for (int kk = 0; kk < 8; kk++) {
            // broadcast LDS.128 x2: 8 batch values for this k
            float4 xa = *(const float4 *)&xs[k + kk][ty * 8];
            float4 xb = *(const float4 *)&xs[k + kk][ty * 8 + 4];
            ull xp[4];
            xp[0] = *(const ull *)&xa.x; xp[1] = *(const ull *)&xa.z;
            xp[2] = *(const ull *)&xb.x; xp[3] = *(const ull *)&xb.z;
            const float *wf = (const float *)&w[kk];
#pragma unroll
            for (int c = 0; c < 4; c++) {
                ull wc = pack2(wf[c]);
#pragma unroll
                for (int i = 0; i < 4; i++) ffma2(acc[c][i], xp[i], wc);
            }
        }
    }

#pragma unroll
    for (int c = 0; c < 4; c++)
#pragma unroll
        for (int i = 0; i < 4; i++) {
            float2 v = *(float2 *)&acc[c][i];
            int bb = ty * 8 + 2 * i;
            atomicAdd(&Y[(size_t)bb * N + j0 + c], v.x);
            atomicAdd(&Y[(size_t)(bb + 1) * N + j0 + c], v.y);
        }
}

__global__ void __launch_bounds__(512)
gemm_q_kernel(const float *__restrict__ X, const float *__restrict__ W) {
    __shared__ float xs[256][32];
    gemm_body(X, W, g_q, 4096, 256, xs);
}
__global__ void __launch_bounds__(512)
gemm_kv_kernel(const float *__restrict__ X, const float *__restrict__ Wk,
               const float *__restrict__ Wv) {
    __shared__ float xs[256][32];
    if (blockIdx.z == 0) gemm_body(X, Wk, g_k, 1024, 128, xs);
    else                 gemm_body(X, Wv, g_v, 1024, 128, xs);
}
__global__ void __launch_bounds__(512)
gemm_o_kernel(const float *__restrict__ W, float *__restrict__ out) {
    __shared__ float xs[256][32];
    gemm_body(g_attn, W, out, 4096, 256, xs);
}

// -------- RoPE --------
__global__ void rope_kernel(const float *__restrict__ fcos,
                            const float *__restrict__ fsin) {
    int idx = blockIdx.x * 256 + threadIdx.x;   // 32*40*64 pairs
    int i = idx & 63;
    int head = (idx >> 6) % 40;
    int bb = idx / (40 * 64);
    float c = fcos[i], s = fsin[i];
    float *base = (head < 32) ? (g_q + (size_t)bb * 4096 + head * 128)
                              : (g_k + (size_t)bb * 1024 + (head - 32) * 128);
    float xr = base[2 * i], xi = base[2 * i + 1];
    base[2 * i]     = xr * c - xi * s;
    base[2 * i + 1] = xr * s + xi * c;
}

// -------- Attention: block per (b, kv); half-warp owns 4 K/V rows per iter --------
__global__ void __launch_bounds__(256)
attn_kernel(const float *__restrict__ kc, const float *__restrict__ vc) {
    const int b = blockIdx.x >> 3;
    const int kv = blockIdx.x & 7;
    const int tid = threadIdx.x;
    const int lane = tid & 31;
    const int wid = tid >> 5;
    const int hl = lane & 15;
    const int half = lane >> 4;

    __shared__ float qs[512];
    __shared__ float sc[4 * T_TOT];
    __shared__ float accs[512];
    __shared__ float red[32];
    __shared__ float gmax[4], gsum[4];

    for (int i = tid; i < 512; i += 256) {
        qs[i] = g_q[(size_t)b * 4096 + kv * 512 + i] * RSQRT_HD;
        accs[i] = 0.f;
    }
    __syncthreads();

    ull qp[4][4];
#pragma unroll
    for (int h = 0; h < 4; h++) {
        const ull *qa = (const ull *)&qs[h * 128 + hl * 4];
        const ull *qb = (const ull *)&qs[h * 128 + hl * 4 + 64];
        qp[h][0] = qa[0]; qp[h][1] = qa[1];
        qp[h][2] = qb[0]; qp[h][3] = qb[1];
    }

    const float *kbase = kc + ((size_t)b * MAXS * NKV + kv) * HD;
    const float *knew  = g_k + (size_t)(b * NKV + kv) * HD;

    // Phase 1: scores. 8 rows per warp-iter (8 LDG.128 in flight per warp)
    for (int tb = wid * 8; tb < T_TOT; tb += 64) {
        int t0 = tb + half, t1 = tb + 2 + half, t2 = tb + 4 + half, t3 = tb + 6 + half;
        const float *k0p = (t0 == START_T) ? knew : kbase + (size_t)t0 * (NKV * HD);
        const float *k1p = (t1 == START_T) ? knew : kbase + (size_t)t1 * (NKV * HD);
        const float *k2p = (t2 == START_T) ? knew : kbase + (size_t)t2 * (NKV * HD);
        const float *k3p = (t3 == START_T) ? knew : kbase + (size_t)t3 * (NKV * HD);
        float4 lo[4], hi[4];
        lo[0] = *(const float4 *)(k0p + hl * 4); hi[0] = *(const float4 *)(k0p + hl * 4 + 64);
        lo[1] = *(const float4 *)(k1p + hl * 4); hi[1] = *(const float4 *)(k1p + hl * 4 + 64);
        lo[2] = *(const float4 *)(k2p + hl * 4); hi[2] = *(const float4 *)(k2p + hl * 4 + 64);
        lo[3] = *(const float4 *)(k3p + hl * 4); hi[3] = *(const float4 *)(k3p + hl * 4 + 64);

        float f[4][4];
#pragma unroll
        for (int r = 0; r < 4; r++) {
            const ull *lp = (const ull *)&lo[r];
            const ull *hp = (const ull *)&hi[r];
#pragma unroll
            for (int h = 0; h < 4; h++) {
                ull s = 0ULL;
                ffma2(s, lp[0], qp[h][0]); ffma2(s, lp[1], qp[h][1]);
                ffma2(s, hp[0], qp[h][2]); ffma2(s, hp[1], qp[h][3]);
                float2 v = *(float2 *)&s;
                f[h][r] = v.x + v.y;
            }
        }
#pragma unroll
        for (int off = 8; off; off >>= 1)
#pragma unroll
            for (int h = 0; h < 4; h++) {
                f[h][0] += __shfl_xor_sync(~0u, f[h][0], off);
                f[h][1] += __shfl_xor_sync(~0u, f[h][1], off);
                f[h][2] += __shfl_xor_sync(~0u, f[h][2], off);
                f[h][3] += __shfl_xor_sync(~0u, f[h][3], off);
            }
        if (hl == 0) {
#pragma unroll
            for (int h = 0; h < 4; h++) {
                sc[h * T_TOT + t0] = f[h][0];
                sc[h * T_TOT + t1] = f[h][1];
                sc[h * T_TOT + t2] = f[h][2];
                sc[h * T_TOT + t3] = f[h][3];
            }
        }
    }
    __syncthreads();

    // Phase 2: softmax (deferred normalization)
    float m0 = -1e30f, m1 = -1e30f, m2 = -1e30f, m3 = -1e30f;
    for (int t = tid; t < T_TOT; t += 256) {
        m0 = fmaxf(m0, sc[t]);
        m1 = fmaxf(m1, sc[T_TOT + t]);
        m2 = fmaxf(m2, sc[2 * T_TOT + t]);
        m3 = fmaxf(m3, sc[3 * T_TOT + t]);
    }
#pragma unroll
    for (int off = 16; off; off >>= 1) {
        m0 = fmaxf(m0, __shfl_xor_sync(~0u, m0, off));
        m1 = fmaxf(m1, __shfl_xor_sync(~0u, m1, off));
        m2 = fmaxf(m2, __shfl_xor_sync(~0u, m2, off));
        m3 = fmaxf(m3, __shfl_xor_sync(~0u, m3, off));
    }
    if (lane == 0) { red[wid * 4 + 0] = m0; red[wid * 4 + 1] = m1;
                     red[wid * 4 + 2] = m2; red[wid * 4 + 3] = m3; }
    __syncthreads();
    if (tid < 4) {
        float m = red[tid];
#pragma unroll
        for (int w = 1; w < 8; w++) m = fmaxf(m, red[w * 4 + tid]);
        gmax[tid] = m;
    }
    __syncthreads();
    m0 = gmax[0]; m1 = gmax[1]; m2 = gmax[2]; m3 = gmax[3];

    float sm0 = 0.f, sm1 = 0.f, sm2 = 0.f, sm3 = 0.f;
    for (int t = tid; t < T_TOT; t += 256) {
        float e0 = __expf(sc[t] - m0);               sc[t] = e0;               sm0 += e0;
        float e1 = __expf(sc[T_TOT + t] - m1);       sc[T_TOT + t] = e1;       sm1 += e1;
        float e2 = __expf(sc[2 * T_TOT + t] - m2);   sc[2 * T_TOT + t] = e2;   sm2 += e2;
        float e3 = __expf(sc[3 * T_TOT + t] - m3);   sc[3 * T_TOT + t] = e3;   sm3 += e3;
    }
#pragma unroll
    for (int off = 16; off; off >>= 1) {
        sm0 += __shfl_xor_sync(~0u, sm0, off);
        sm1 += __shfl_xor_sync(~0u, sm1, off);
        sm2 += __shfl_xor_sync(~0u, sm2, off);
        sm3 += __shfl_xor_sync(~0u, sm3, off);
    }
    __syncthreads();
    if (lane == 0) { red[wid * 4 + 0] = sm0; red[wid * 4 + 1] = sm1;
                     red[wid * 4 + 2] = sm2; red[wid * 4 + 3] = sm3; }
    __syncthreads();
    if (tid < 4) {
        float s = 0.f;
#pragma unroll
        for (int w = 0; w < 8; w++) s += red[w * 4 + tid];
        gsum[tid] = 1.0f / s;
    }
    __syncthreads();

    // Phase 3: P @ V, same 8-rows-per-iter layout
    ull oa[4][4];
#pragma unroll
    for (int h = 0; h < 4; h++)
#pragma unroll
        for (int j = 0; j < 4; j++) oa[h][j] = 0ULL;

    const float *vbase = vc + ((size_t)b * MAXS * NKV + kv) * HD;
    const float *vnew  = g_v + (size_t)(b * NKV + kv) * HD;
    for (int tb = wid * 8; tb < T_TOT; tb += 64) {
        int t0 = tb + half, t1 = tb + 2 + half, t2 = tb + 4 + half, t3 = tb + 6 + half;
        const float *v0p = (t0 == START_T) ? vnew : vbase + (size_t)t0 * (NKV * HD);
        const float *v1p = (t1 == START_T) ? vnew : vbase + (size_t)t1 * (NKV * HD);
        const float *v2p = (t2 == START_T) ? vnew : vbase + (size_t)t2 * (NKV * HD);
        const float *v3p = (t3 == START_T) ? vnew : vbase + (size_t)t3 * (NKV * HD);
        float4 lo[4], hi[4];
        lo[0] = *(const float4 *)(v0p + hl * 4); hi[0] = *(const float4 *)(v0p + hl * 4 + 64);
        lo[1] = *(const float4 *)(v1p + hl * 4); hi[1] = *(const float4 *)(v1p + hl * 4 + 64);
        lo[2] = *(const float4 *)(v2p + hl * 4); hi[2] = *(const float4 *)(v2p + hl * 4 + 64);
        lo[3] = *(const float4 *)(v3p + hl * 4); hi[3] = *(const float4 *)(v3p + hl * 4 + 64);
        int tt[4] = {t0, t1, t2, t3};
#pragma unroll
        for (int r = 0; r < 4; r++) {
            const ull *lp = (const ull *)&lo[r];
            const ull *hp = (const ull *)&hi[r];
#pragma unroll
            for (int h = 0; h < 4; h++) {
                ull p = pack2(sc[h * T_TOT + tt[r]]);
                ffma2(oa[h][0], lp[0], p); ffma2(oa[h][1], lp[1], p);
                ffma2(oa[h][2], hp[0], p); ffma2(oa[h][3], hp[1], p);
            }
        }
    }

#pragma unroll
    for (int h = 0; h < 4; h++)
#pragma unroll
        for (int j = 0; j < 4; j++) {
            float2 v = *(float2 *)&oa[h][j];
            v.x += __shfl_xor_sync(~0u, v.x, 16);
            v.y += __shfl_xor_sync(~0u, v.y, 16);
            if (half == 0) {
                int d = hl * 4 + (j & 1) * 2 + (j >> 1) * 64;
                atomicAdd(&accs[h * 128 + d], v.x);
                atomicAdd(&accs[h * 128 + d + 1], v.y);
            }
        }
    __syncthreads();

    for (int i = tid; i < 512; i += 256) {
        int h = i >> 7, d = i & 127;
        g_attn[(size_t)b * 4096 + (kv * 4 + h) * 128 + d] = accs[i] * gsum[h];
    }
}

extern "C" void kernel_launch(void *const *d_in, const int *in_sizes, int n_in,
                              void *d_out, int out_size) {
    const float *x    = (const float *)d_in[0];
    const float *wq   = (const float *)d_in[1];
    const float *wk   = (const float *)d_in[2];
    const float *wv   = (const float *)d_in[3];
    const float *wo   = (const float *)d_in[4];
    const float *kc   = (const float *)d_in[5];
    const float *vc   = (const float *)d_in[6];
    const float *fcos = (const float *)d_in[7];
    const float *fsin = (const float *)d_in[8];
    float *out = (float *)d_out;

    zero_kernel<<<320, 256>>>(out);

    gemm_q_kernel<<<dim3(8, 16), 512>>>(x, wq);           // 128 CTAs, KB=256
    gemm_kv_kernel<<<dim3(2, 32, 2), 512>>>(x, wk, wv);   // 128 CTAs, KB=128

    rope_kernel<<<320, 256>>>(fcos, fsin);

    attn_kernel<<<BATCH * NKV, 256>>>(kc, vc);

    gemm_o_kernel<<<dim3(8, 16), 512>>>(wo, out);         // 128 CTAs, KB=256
}

// round 8
// speedup vs baseline: 1.7729x; 1.0242x over previous
#include <cuda_runtime.h>
#include <math.h>

typedef unsigned long long ull;

#define BATCH   32
#define DIM     4096
#define NH      32
#define NKV     8
#define HD      128
#define MAXS    2048
#define START_T 2047
#define T_TOT   2048
#define RSQRT_HD 0.088388347648318447f

// -------- device scratch --------
__device__ float g_q[BATCH * NH * HD];
__device__ float g_k[BATCH * NKV * HD];
__device__ float g_v[BATCH * NKV * HD];
__device__ float g_attn[BATCH * NH * HD];

// -------- packed f32x2 helpers --------
__device__ __forceinline__ void ffma2(ull &acc, ull a, ull b) {
    asm("fma.rn.f32x2 %0, %1, %2, %0;" : "+l"(acc) : "l"(a), "l"(b));
}
__device__ __forceinline__ ull pack2(float w) {
    ull r; unsigned u = __float_as_uint(w);
    asm("mov.b64 %0, {%1, %1};" : "=l"(r) : "r"(u));
    return r;
}

// -------- zero scratch + output --------
__global__ void zero_kernel(float *__restrict__ out) {
    int i = blockIdx.x * 256 + threadIdx.x;
    for (; i < 327680; i += 81920) {
        if (i < 131072)       g_q[i] = 0.f;
        else if (i < 163840)  g_k[i - 131072] = 0.f;
        else if (i < 196608)  g_v[i - 163840] = 0.f;
        else                  out[i - 196608] = 0.f;
    }
}

// -------- GEMM body: Y[32,N] += X[32,4096] @ W[4096,N] --------
// 512 threads: thread = 4 cols x 8 batches; 8-deep W-load hoist.
__device__ __forceinline__ void gemm_body(const float *__restrict__ X,
                                          const float *__restrict__ W,
                                          float *__restrict__ Y, int N, int KB,
                                          int jblock, int kbeg,
                                          float (*xs)[32]) {
    const int tid = threadIdx.x;
    const int tx = tid & 127;
    const int ty = tid >> 7;
    const int j0 = jblock + tx * 4;

    const int nc4 = KB >> 2;
    for (int idx = tid; idx < 32 * nc4; idx += 512) {
        int bb = idx & 31, c = idx >> 5;
        float4 xv = *(const float4 *)(X + (size_t)bb * DIM + kbeg + 4 * c);
        xs[4 * c + 0][bb] = xv.x; xs[4 * c + 1][bb] = xv.y;
        xs[4 * c + 2][bb] = xv.z; xs[4 * c + 3][bb] = xv.w;
    }
    __syncthreads();

    ull acc[4][4];
#pragma unroll
    for (int c = 0; c < 4; c++)
#pragma unroll
        for (int i = 0; i < 4; i++) acc[c][i] = 0ULL;

    const float *wp = W + (size_t)kbeg * N + j0;
    for (int k = 0; k < KB; k += 8) {
        const float *wk8 = wp + (size_t)k * N;
        float4 w[8];
#pragma unroll
        for (int kk = 0; kk < 8; kk++)
            w[kk] = *(const float4 *)(wk8 + (size_t)kk * N);
#pragma unroll
        for (int kk = 0; kk < 8; kk++) {
            float4 xa = *(const float4 *)&xs[k + kk][ty * 8];
            float4 xb = *(const float4 *)&xs[k + kk][ty * 8 + 4];
            ull xp[4];
            xp[0] = *(const ull *)&xa.x; xp[1] = *(const ull *)&xa.z;
            xp[2] = *(const ull *)&xb.x; xp[3] = *(const ull *)&xb.z;
            const float *wf = (const float *)&w[kk];
#pragma unroll
            for (int c = 0; c < 4; c++) {
                ull wc = pack2(wf[c]);
#pragma unroll
                for (int i = 0; i < 4; i++) ffma2(acc[c][i], xp[i], wc);
            }
        }
    }

#pragma unroll
    for (int c = 0; c < 4; c++)
#pragma unroll
        for (int i = 0; i < 4; i++) {
            float2 v = *(float2 *)&acc[c][i];
            int bb = ty * 8 + 2 * i;
            atomicAdd(&Y[(size_t)bb * N + j0 + c], v.x);
            atomicAdd(&Y[(size_t)(bb + 1) * N + j0 + c], v.y);
        }
}

// Merged QKV: CTAs 0-127 wq (KB=256), 128-191 wk, 192-255 wv (KB=128)
__global__ void __launch_bounds__(512)
gemm_qkv_kernel(const float *__restrict__ X, const float *__restrict__ Wq,
                const float *__restrict__ Wk, const float *__restrict__ Wv) {
    __shared__ float xs[256][32];
    int id = blockIdx.x;
    if (id < 128) {
        gemm_body(X, Wq, g_q, 4096, 256, (id & 7) * 512, (id >> 3) * 256, xs);
    } else {
        int id2 = id - 128;                       // 0..127
        const float *W = (id2 & 64) ? Wv : Wk;
        float *Y = (id2 & 64) ? g_v : g_k;
        int jb = id2 & 1;                         // 2 j-blocks of 512
        int ks = (id2 >> 1) & 31;                 // 32 k-splits of 128
        gemm_body(X, W, Y, 1024, 128, jb * 512, ks * 128, xs);
    }
}

__global__ void __launch_bounds__(512)
gemm_o_kernel(const float *__restrict__ W, float *__restrict__ out) {
    __shared__ float xs[256][32];
    gemm_body(g_attn, W, out, 4096, 256, blockIdx.x * 512, blockIdx.y * 256, xs);
}

// -------- Attention with fused RoPE: block per (b, kv) --------
__global__ void __launch_bounds__(256)
attn_kernel(const float *__restrict__ kc, const float *__restrict__ vc,
            const float *__restrict__ fcos, const float *__restrict__ fsin) {
    const int b = blockIdx.x >> 3;
    const int kv = blockIdx.x & 7;
    const int tid = threadIdx.x;
    const int lane = tid & 31;
    const int wid = tid >> 5;
    const int hl = lane & 15;
    const int half = lane >> 4;

    __shared__ float qs[512];
    __shared__ float sc[4 * T_TOT];
    __shared__ float accs[512];
    __shared__ float red[32];
    __shared__ float gmax[4], gsum[4];

    // RoPE q while staging into smem (one pair per thread), pre-scaled
    {
        int h = tid >> 6, i = tid & 63;
        float c = fcos[i], s = fsin[i];
        const float *qb = g_q + (size_t)b * 4096 + kv * 512 + h * 128 + 2 * i;
        float xr = qb[0], xi = qb[1];
        qs[h * 128 + 2 * i]     = (xr * c - xi * s) * RSQRT_HD;
        qs[h * 128 + 2 * i + 1] = (xr * s + xi * c) * RSQRT_HD;
    }
    for (int i = tid; i < 512; i += 256) accs[i] = 0.f;
    // RoPE the new K row in place (block-exclusive row of g_k)
    if (tid < 64) {
        int i = tid;
        float c = fcos[i], s = fsin[i];
        float *kb2 = g_k + (size_t)(b * NKV + kv) * HD + 2 * i;
        float xr = kb2[0], xi = kb2[1];
        kb2[0] = xr * c - xi * s;
        kb2[1] = xr * s + xi * c;
    }
    __syncthreads();

    ull qp[4][4];
#pragma unroll
    for (int h = 0; h < 4; h++) {
        const ull *qa = (const ull *)&qs[h * 128 + hl * 4];
        const ull *qb = (const ull *)&qs[h * 128 + hl * 4 + 64];
        qp[h][0] = qa[0]; qp[h][1] = qa[1];
        qp[h][2] = qb[0]; qp[h][3] = qb[1];
    }

    const float *kbase = kc + ((size_t)b * MAXS * NKV + kv) * HD;
    const float *knew  = g_k + (size_t)(b * NKV + kv) * HD;

    // Phase 1: scores. 8 rows per warp-iter (8 LDG.128 in flight per warp)
    for (int tb = wid * 8; tb < T_TOT; tb += 64) {
        int t0 = tb + half, t1 = tb + 2 + half, t2 = tb + 4 + half, t3 = tb + 6 + half;
        const float *k0p = (t0 == START_T) ? knew : kbase + (size_t)t0 * (NKV * HD);
        const float *k1p = (t1 == START_T) ? knew : kbase + (size_t)t1 * (NKV * HD);
        const float *k2p = (t2 == START_T) ? knew : kbase + (size_t)t2 * (NKV * HD);
        const float *k3p = (t3 == START_T) ? knew : kbase + (size_t)t3 * (NKV * HD);
        float4 lo[4], hi[4];
        lo[0] = *(const float4 *)(k0p + hl * 4); hi[0] = *(const float4 *)(k0p + hl * 4 + 64);
        lo[1] = *(const float4 *)(k1p + hl * 4); hi[1] = *(const float4 *)(k1p + hl * 4 + 64);
        lo[2] = *(const float4 *)(k2p + hl * 4); hi[2] = *(const float4 *)(k2p + hl * 4 + 64);
        lo[3] = *(const float4 *)(k3p + hl * 4); hi[3] = *(const float4 *)(k3p + hl * 4 + 64);

        float f[4][4];
#pragma unroll
        for (int r = 0; r < 4; r++) {
            const ull *lp = (const ull *)&lo[r];
            const ull *hp = (const ull *)&hi[r];
#pragma unroll
            for (int h = 0; h < 4; h++) {
                ull s = 0ULL;
                ffma2(s, lp[0], qp[h][0]); ffma2(s, lp[1], qp[h][1]);
                ffma2(s, hp[0], qp[h][2]); ffma2(s, hp[1], qp[h][3]);
                float2 v = *(float2 *)&s;
                f[h][r] = v.x + v.y;
            }
        }
#pragma unroll
        for (int off = 8; off; off >>= 1)
#pragma unroll
            for (int h = 0; h < 4; h++) {
                f[h][0] += __shfl_xor_sync(~0u, f[h][0], off);
                f[h][1] += __shfl_xor_sync(~0u, f[h][1], off);
                f[h][2] += __shfl_xor_sync(~0u, f[h][2], off);
                f[h][3] += __shfl_xor_sync(~0u, f[h][3], off);
            }
        if (hl == 0) {
#pragma unroll
            for (int h = 0; h < 4; h++) {
                sc[h * T_TOT + t0] = f[h][0];
                sc[h * T_TOT + t1] = f[h][1];
                sc[h * T_TOT + t2] = f[h][2];
                sc[h * T_TOT + t3] = f[h][3];
            }
        }
    }
    __syncthreads();

    // Phase 2: softmax (deferred normalization)
    float m0 = -1e30f, m1 = -1e30f, m2 = -1e30f, m3 = -1e30f;
    for (int t = tid; t < T_TOT; t += 256) {
        m0 = fmaxf(m0, sc[t]);
        m1 = fmaxf(m1, sc[T_TOT + t]);
        m2 = fmaxf(m2, sc[2 * T_TOT + t]);
        m3 = fmaxf(m3, sc[3 * T_TOT + t]);
    }
#pragma unroll
    for (int off = 16; off; off >>= 1) {
        m0 = fmaxf(m0, __shfl_xor_sync(~0u, m0, off));
        m1 = fmaxf(m1, __shfl_xor_sync(~0u, m1, off));
        m2 = fmaxf(m2, __shfl_xor_sync(~0u, m2, off));
        m3 = fmaxf(m3, __shfl_xor_sync(~0u, m3, off));
    }
    if (lane == 0) { red[wid * 4 + 0] = m0; red[wid * 4 + 1] = m1;
                     red[wid * 4 + 2] = m2; red[wid * 4 + 3] = m3; }
    __syncthreads();
    if (tid < 4) {
        float m = red[tid];
#pragma unroll
        for (int w = 1; w < 8; w++) m = fmaxf(m, red[w * 4 + tid]);
        gmax[tid] = m;
    }
    __syncthreads();
    m0 = gmax[0]; m1 = gmax[1]; m2 = gmax[2]; m3 = gmax[3];

    float sm0 = 0.f, sm1 = 0.f, sm2 = 0.f, sm3 = 0.f;
    for (int t = tid; t < T_TOT; t += 256) {
        float e0 = __expf(sc[t] - m0);               sc[t] = e0;               sm0 += e0;
        float e1 = __expf(sc[T_TOT + t] - m1);       sc[T_TOT + t] = e1;       sm1 += e1;
        float e2 = __expf(sc[2 * T_TOT + t] - m2);   sc[2 * T_TOT + t] = e2;   sm2 += e2;
        float e3 = __expf(sc[3 * T_TOT + t] - m3);   sc[3 * T_TOT + t] = e3;   sm3 += e3;
    }
#pragma unroll
    for (int off = 16; off; off >>= 1) {
        sm0 += __shfl_xor_sync(~0u, sm0, off);
        sm1 += __shfl_xor_sync(~0u, sm1, off);
        sm2 += __shfl_xor_sync(~0u, sm2, off);
        sm3 += __shfl_xor_sync(~0u, sm3, off);
    }
    __syncthreads();
    if (lane == 0) { red[wid * 4 + 0] = sm0; red[wid * 4 + 1] = sm1;
                     red[wid * 4 + 2] = sm2; red[wid * 4 + 3] = sm3; }
    __syncthreads();
    if (tid < 4) {
        float s = 0.f;
#pragma unroll
        for (int w = 0; w < 8; w++) s += red[w * 4 + tid];
        gsum[tid] = 1.0f / s;
    }
    __syncthreads();

    // Phase 3: P @ V, same 8-rows-per-iter layout
    ull oa[4][4];
#pragma unroll
    for (int h = 0; h < 4; h++)
#pragma unroll
        for (int j = 0; j < 4; j++) oa[h][j] = 0ULL;

    const float *vbase = vc + ((size_t)b * MAXS * NKV + kv) * HD;
    const float *vnew  = g_v + (size_t)(b * NKV + kv) * HD;
    for (int tb = wid * 8; tb < T_TOT; tb += 64) {
        int t0 = tb + half, t1 = tb + 2 + half, t2 = tb + 4 + half, t3 = tb + 6 + half;
        const float *v0p = (t0 == START_T) ? vnew : vbase + (size_t)t0 * (NKV * HD);
        const float *v1p = (t1 == START_T) ? vnew : vbase + (size_t)t1 * (NKV * HD);
        const float *v2p = (t2 == START_T) ? vnew : vbase + (size_t)t2 * (NKV * HD);
        const float *v3p = (t3 == START_T) ? vnew : vbase + (size_t)t3 * (NKV * HD);
        float4 lo[4], hi[4];
        lo[0] = *(const float4 *)(v0p + hl * 4); hi[0] = *(const float4 *)(v0p + hl * 4 + 64);
        lo[1] = *(const float4 *)(v1p + hl * 4); hi[1] = *(const float4 *)(v1p + hl * 4 + 64);
        lo[2] = *(const float4 *)(v2p + hl * 4); hi[2] = *(const float4 *)(v2p + hl * 4 + 64);
        lo[3] = *(const float4 *)(v3p + hl * 4); hi[3] = *(const float4 *)(v3p + hl * 4 + 64);
        int tt[4] = {t0, t1, t2, t3};
#pragma unroll
        for (int r = 0; r < 4; r++) {
            const ull *lp = (const ull *)&lo[r];
            const ull *hp = (const ull *)&hi[r];
#pragma unroll
            for (int h = 0; h < 4; h++) {
                ull p = pack2(sc[h * T_TOT + tt[r]]);
                ffma2(oa[h][0], lp[0], p); ffma2(oa[h][1], lp[1], p);
                ffma2(oa[h][2], hp[0], p); ffma2(oa[h][3], hp[1], p);
            }
        }
    }

#pragma unroll
    for (int h = 0; h < 4; h++)
#pragma unroll
        for (int j = 0; j < 4; j++) {
            float2 v = *(float2 *)&oa[h][j];
            v.x += __shfl_xor_sync(~0u, v.x, 16);
            v.y += __shfl_xor_sync(~0u, v.y, 16);
            if (half == 0) {
                int d = hl * 4 + (j & 1) * 2 + (j >> 1) * 64;
                atomicAdd(&accs[h * 128 + d], v.x);
                atomicAdd(&accs[h * 128 + d + 1], v.y);
            }
        }
    __syncthreads();

    for (int i = tid; i < 512; i += 256) {
        int h = i >> 7, d = i & 127;
        g_attn[(size_t)b * 4096 + (kv * 4 + h) * 128 + d] = accs[i] * gsum[h];
    }
}

extern "C" void kernel_launch(void *const *d_in, const int *in_sizes, int n_in,
                              void *d_out, int out_size) {
    const float *x    = (const float *)d_in[0];
    const float *wq   = (const float *)d_in[1];
    const float *wk   = (const float *)d_in[2];
    const float *wv   = (const float *)d_in[3];
    const float *wo   = (const float *)d_in[4];
    const float *kc   = (const float *)d_in[5];
    const float *vc   = (const float *)d_in[6];
    const float *fcos = (const float *)d_in[7];
    const float *fsin = (const float *)d_in[8];
    float *out = (float *)d_out;

    zero_kernel<<<320, 256>>>(out);                       // launch 0
    gemm_qkv_kernel<<<256, 512>>>(x, wq, wk, wv);         // launch 1
    attn_kernel<<<BATCH * NKV, 256>>>(kc, vc, fcos, fsin);// launch 2
    gemm_o_kernel<<<dim3(8, 16), 512>>>(wo, out);         // launch 3 <- ncu capture
}

// round 11
// speedup vs baseline: 2.1375x; 1.2056x over previous
#include <cuda_runtime.h>
#include <math.h>

typedef unsigned long long ull;

#define BATCH   32
#define DIM     4096
#define NH      32
#define NKV     8
#define HD      128
#define MAXS    2048
#define START_T 2047
#define T_TOT   2048
#define RSQRT_HD 0.088388347648318447f

// -------- device scratch --------
__device__ float g_q[BATCH * NH * HD];
__device__ float g_k[BATCH * NKV * HD];
__device__ float g_v[BATCH * NKV * HD];
__device__ float g_attn[BATCH * NH * HD];

// -------- packed f32x2 helpers --------
__device__ __forceinline__ void ffma2(ull &acc, ull a, ull b) {
    asm("fma.rn.f32x2 %0, %1, %2, %0;" : "+l"(acc) : "l"(a), "l"(b));
}
__device__ __forceinline__ ull pack2(float w) {
    ull r; unsigned u = __float_as_uint(w);
    asm("mov.b64 %0, {%1, %1};" : "=l"(r) : "r"(u));
    return r;
}
__device__ __forceinline__ void red_add_v4(float *p, float a, float b, float c,
                                           float d) {
    asm volatile("red.global.add.v4.f32 [%0], {%1, %2, %3, %4};"
                 :: "l"(p), "f"(a), "f"(b), "f"(c), "f"(d) : "memory");
}

// -------- zero scratch + output --------
__global__ void zero_kernel(float *__restrict__ out) {
    int i = blockIdx.x * 256 + threadIdx.x;
    for (; i < 327680; i += 81920) {
        if (i < 131072)       g_q[i] = 0.f;
        else if (i < 163840)  g_k[i - 131072] = 0.f;
        else if (i < 196608)  g_v[i - 163840] = 0.f;
        else                  out[i - 196608] = 0.f;
    }
}

// -------- GEMM body: Y[32,N] += X[32,4096] @ W[4096,N] --------
// 256 threads, CTA tile = 256 cols x 32 batches, KB=128 K-split.
// Thread = 4 cols x 8 batches; k-unroll 4 (w[4] regs).
__device__ __forceinline__ void gemm_body(const float *__restrict__ X,
                                          const float *__restrict__ W,
                                          float *__restrict__ Y, int N,
                                          int jblock, int kbeg,
                                          float (*xs)[32]) {
    const int tid = threadIdx.x;
    const int tx = tid & 63;          // 64 col-groups of 4
    const int ty = tid >> 6;          // 4 batch-octets
    const int j0 = jblock + tx * 4;

    // stage x[kbeg:kbeg+128][0:32] transposed; bb=idx&31 -> conflict-free
    for (int idx = tid; idx < 1024; idx += 256) {
        int bb = idx & 31, c = idx >> 5;
        float4 xv = *(const float4 *)(X + (size_t)bb * DIM + kbeg + 4 * c);
        xs[4 * c + 0][bb] = xv.x; xs[4 * c + 1][bb] = xv.y;
        xs[4 * c + 2][bb] = xv.z; xs[4 * c + 3][bb] = xv.w;
    }
    __syncthreads();

    ull acc[4][4];
#pragma unroll
    for (int c = 0; c < 4; c++)
#pragma unroll
        for (int i = 0; i < 4; i++) acc[c][i] = 0ULL;

    const float *wp = W + (size_t)kbeg * N + j0;
    for (int k = 0; k < 128; k += 4) {
        const float *wk4 = wp + (size_t)k * N;
        float4 w[4];
#pragma unroll
        for (int kk = 0; kk < 4; kk++)
            w[kk] = *(const float4 *)(wk4 + (size_t)kk * N);
#pragma unroll
        for (int kk = 0; kk < 4; kk++) {
            float4 xa = *(const float4 *)&xs[k + kk][ty * 8];
            float4 xb = *(const float4 *)&xs[k + kk][ty * 8 + 4];
            ull xp[4];
            xp[0] = *(const ull *)&xa.x; xp[1] = *(const ull *)&xa.z;
            xp[2] = *(const ull *)&xb.x; xp[3] = *(const ull *)&xb.z;
            const float *wf = (const float *)&w[kk];
#pragma unroll
            for (int c = 0; c < 4; c++) {
                ull wc = pack2(wf[c]);
#pragma unroll
                for (int i = 0; i < 4; i++) ffma2(acc[c][i], xp[i], wc);
            }
        }
    }

    // epilogue: repack batch-pair accs into per-batch col vectors, red.v4
#pragma unroll
    for (int i = 0; i < 4; i++) {
        int bb = ty * 8 + 2 * i;
        float2 v0 = *(float2 *)&acc[0][i];
        float2 v1 = *(float2 *)&acc[1][i];
        float2 v2 = *(float2 *)&acc[2][i];
        float2 v3 = *(float2 *)&acc[3][i];
        red_add_v4(&Y[(size_t)bb * N + j0], v0.x, v1.x, v2.x, v3.x);
        red_add_v4(&Y[(size_t)(bb + 1) * N + j0], v0.y, v1.y, v2.y, v3.y);
    }
}

// Merged QKV: 768 CTAs. 0-511 wq (16 jb x 32 ks), 512-639 wk, 640-767 wv (4 jb x 32 ks)
__global__ void __launch_bounds__(256, 4)
gemm_qkv_kernel(const float *__restrict__ X, const float *__restrict__ Wq,
                const float *__restrict__ Wk, const float *__restrict__ Wv) {
    __shared__ float xs[128][32];
    int id = blockIdx.x;
    if (id < 512) {
        gemm_body(X, Wq, g_q, 4096, (id & 15) * 256, (id >> 4) * 128, xs);
    } else {
        int id2 = id - 512;                 // 0..255
        const float *W = (id2 & 128) ? Wv : Wk;
        float *Y = (id2 & 128) ? g_v : g_k;
        int id3 = id2 & 127;
        gemm_body(X, W, Y, 1024, (id3 & 3) * 256, (id3 >> 2) * 128, xs);
    }
}

__global__ void __launch_bounds__(256, 4)
gemm_o_kernel(const float *__restrict__ W, float *__restrict__ out) {
    __shared__ float xs[128][32];
    gemm_body(g_attn, W, out, 4096, blockIdx.x * 256, blockIdx.y * 128, xs);
}

// -------- Attention with fused RoPE: block per (b, kv) --------
__global__ void __launch_bounds__(256)
attn_kernel(const float *__restrict__ kc, const float *__restrict__ vc,
            const float *__restrict__ fcos, const float *__restrict__ fsin) {
    const int b = blockIdx.x >> 3;
    const int kv = blockIdx.x & 7;
    const int tid = threadIdx.x;
    const int lane = tid & 31;
    const int wid = tid >> 5;
    const int hl = lane & 15;
    const int half = lane >> 4;

    __shared__ float qs[512];
    __shared__ float sc[4 * T_TOT];
    __shared__ float accs[512];
    __shared__ float red[32];
    __shared__ float gmax[4], gsum[4];

    // RoPE q while staging into smem (one pair per thread), pre-scaled
    {
        int h = tid >> 6, i = tid & 63;
        float c = fcos[i], s = fsin[i];
        const float *qb = g_q + (size_t)b * 4096 + kv * 512 + h * 128 + 2 * i;
        float xr = qb[0], xi = qb[1];
        qs[h * 128 + 2 * i]     = (xr * c - xi * s) * RSQRT_HD;
        qs[h * 128 + 2 * i + 1] = (xr * s + xi * c) * RSQRT_HD;
    }
    for (int i = tid; i < 512; i += 256) accs[i] = 0.f;
    // RoPE the new K row in place (block-exclusive row of g_k)
    if (tid < 64) {
        int i = tid;
        float c = fcos[i], s = fsin[i];
        float *kb2 = g_k + (size_t)(b * NKV + kv) * HD + 2 * i;
        float xr = kb2[0], xi = kb2[1];
        kb2[0] = xr * c - xi * s;
        kb2[1] = xr * s + xi * c;
    }
    __syncthreads();

    ull qp[4][4];
#pragma unroll
    for (int h = 0; h < 4; h++) {
        const ull *qa = (const ull *)&qs[h * 128 + hl * 4];
        const ull *qb = (const ull *)&qs[h * 128 + hl * 4 + 64];
        qp[h][0] = qa[0]; qp[h][1] = qa[1];
        qp[h][2] = qb[0]; qp[h][3] = qb[1];
    }

    const float *kbase = kc + ((size_t)b * MAXS * NKV + kv) * HD;
    const float *knew  = g_k + (size_t)(b * NKV + kv) * HD;

    // Phase 1: scores. 8 rows per warp-iter (8 LDG.128 in flight per warp)
    for (int tb = wid * 8; tb < T_TOT; tb += 64) {
        int t0 = tb + half, t1 = tb + 2 + half, t2 = tb + 4 + half, t3 = tb + 6 + half;
        const float *k0p = (t0 == START_T) ? knew : kbase + (size_t)t0 * (NKV * HD);
        const float *k1p = (t1 == START_T) ? knew : kbase + (size_t)t1 * (NKV * HD);
        const float *k2p = (t2 == START_T) ? knew : kbase + (size_t)t2 * (NKV * HD);
        const float *k3p = (t3 == START_T) ? knew : kbase + (size_t)t3 * (NKV * HD);
        float4 lo[4], hi[4];
        lo[0] = *(const float4 *)(k0p + hl * 4); hi[0] = *(const float4 *)(k0p + hl * 4 + 64);
        lo[1] = *(const float4 *)(k1p + hl * 4); hi[1] = *(const float4 *)(k1p + hl * 4 + 64);
        lo[2] = *(const float4 *)(k2p + hl * 4); hi[2] = *(const float4 *)(k2p + hl * 4 + 64);
        lo[3] = *(const float4 *)(k3p + hl * 4); hi[3] = *(const float4 *)(k3p + hl * 4 + 64);

        float f[4][4];
#pragma unroll
        for (int r = 0; r < 4; r++) {
            const ull *lp = (const ull *)&lo[r];
            const ull *hp = (const ull *)&hi[r];
#pragma unroll
            for (int h = 0; h < 4; h++) {
                ull s = 0ULL;
                ffma2(s, lp[0], qp[h][0]); ffma2(s, lp[1], qp[h][1]);
                ffma2(s, hp[0], qp[h][2]); ffma2(s, hp[1], qp[h][3]);
                float2 v = *(float2 *)&s;
                f[h][r] = v.x + v.y;
            }
        }
#pragma unroll
        for (int off = 8; off; off >>= 1)
#pragma unroll
            for (int h = 0; h < 4; h++) {
                f[h][0] += __shfl_xor_sync(~0u, f[h][0], off);
                f[h][1] += __shfl_xor_sync(~0u, f[h][1], off);
                f[h][2] += __shfl_xor_sync(~0u, f[h][2], off);
                f[h][3] += __shfl_xor_sync(~0u, f[h][3], off);
            }
        if (hl == 0) {
#pragma unroll
            for (int h = 0; h < 4; h++) {
                sc[h * T_TOT + t0] = f[h][0];
                sc[h * T_TOT + t1] = f[h][1];
                sc[h * T_TOT + t2] = f[h][2];
                sc[h * T_TOT + t3] = f[h][3];
            }
        }
    }
    __syncthreads();

    // Phase 2: softmax (deferred normalization)
    float m0 = -1e30f, m1 = -1e30f, m2 = -1e30f, m3 = -1e30f;
    for (int t = tid; t < T_TOT; t += 256) {
        m0 = fmaxf(m0, sc[t]);
        m1 = fmaxf(m1, sc[T_TOT + t]);
        m2 = fmaxf(m2, sc[2 * T_TOT + t]);
        m3 = fmaxf(m3, sc[3 * T_TOT + t]);
    }
#pragma unroll
    for (int off = 16; off; off >>= 1) {
        m0 = fmaxf(m0, __shfl_xor_sync(~0u, m0, off));
        m1 = fmaxf(m1, __shfl_xor_sync(~0u, m1, off));
        m2 = fmaxf(m2, __shfl_xor_sync(~0u, m2, off));
        m3 = fmaxf(m3, __shfl_xor_sync(~0u, m3, off));
    }
    if (lane == 0) { red[wid * 4 + 0] = m0; red[wid * 4 + 1] = m1;
                     red[wid * 4 + 2] = m2; red[wid * 4 + 3] = m3; }
    __syncthreads();
    if (tid < 4) {
        float m = red[tid];
#pragma unroll
        for (int w = 1; w < 8; w++) m = fmaxf(m, red[w * 4 + tid]);
        gmax[tid] = m;
    }
    __syncthreads();
    m0 = gmax[0]; m1 = gmax[1]; m2 = gmax[2]; m3 = gmax[3];

    float sm0 = 0.f, sm1 = 0.f, sm2 = 0.f, sm3 = 0.f;
    for (int t = tid; t < T_TOT; t += 256) {
        float e0 = __expf(sc[t] - m0);               sc[t] = e0;               sm0 += e0;
        float e1 = __expf(sc[T_TOT + t] - m1);       sc[T_TOT + t] = e1;       sm1 += e1;
        float e2 = __expf(sc[2 * T_TOT + t] - m2);   sc[2 * T_TOT + t] = e2;   sm2 += e2;
        float e3 = __expf(sc[3 * T_TOT + t] - m3);   sc[3 * T_TOT + t] = e3;   sm3 += e3;
    }
#pragma unroll
    for (int off = 16; off; off >>= 1) {
        sm0 += __shfl_xor_sync(~0u, sm0, off);
        sm1 += __shfl_xor_sync(~0u, sm1, off);
        sm2 += __shfl_xor_sync(~0u, sm2, off);
        sm3 += __shfl_xor_sync(~0u, sm3, off);
    }
    __syncthreads();
    if (lane == 0) { red[wid * 4 + 0] = sm0; red[wid * 4 + 1] = sm1;
                     red[wid * 4 + 2] = sm2; red[wid * 4 + 3] = sm3; }
    __syncthreads();
    if (tid < 4) {
        float s = 0.f;
#pragma unroll
        for (int w = 0; w < 8; w++) s += red[w * 4 + tid];
        gsum[tid] = 1.0f / s;
    }
    __syncthreads();

    // Phase 3: P @ V, same 8-rows-per-iter layout
    ull oa[4][4];
#pragma unroll
    for (int h = 0; h < 4; h++)
#pragma unroll
        for (int j = 0; j < 4; j++) oa[h][j] = 0ULL;

    const float *vbase = vc + ((size_t)b * MAXS * NKV + kv) * HD;
    const float *vnew  = g_v + (size_t)(b * NKV + kv) * HD;
    for (int tb = wid * 8; tb < T_TOT; tb += 64) {
        int t0 = tb + half, t1 = tb + 2 + half, t2 = tb + 4 + half, t3 = tb + 6 + half;
        const float *v0p = (t0 == START_T) ? vnew : vbase + (size_t)t0 * (NKV * HD);
        const float *v1p = (t1 == START_T) ? vnew : vbase + (size_t)t1 * (NKV * HD);
        const float *v2p = (t2 == START_T) ? vnew : vbase + (size_t)t2 * (NKV * HD);
        const float *v3p = (t3 == START_T) ? vnew : vbase + (size_t)t3 * (NKV * HD);
        float4 lo[4], hi[4];
        lo[0] = *(const float4 *)(v0p + hl * 4); hi[0] = *(const float4 *)(v0p + hl * 4 + 64);
        lo[1] = *(const float4 *)(v1p + hl * 4); hi[1] = *(const float4 *)(v1p + hl * 4 + 64);
        lo[2] = *(const float4 *)(v2p + hl * 4); hi[2] = *(const float4 *)(v2p + hl * 4 + 64);
        lo[3] = *(const float4 *)(v3p + hl * 4); hi[3] = *(const float4 *)(v3p + hl * 4 + 64);
        int tt[4] = {t0, t1, t2, t3};
#pragma unroll
        for (int r = 0; r < 4; r++) {
            const ull *lp = (const ull *)&lo[r];
            const ull *hp = (const ull *)&hi[r];
#pragma unroll
            for (int h = 0; h < 4; h++) {
                ull p = pack2(sc[h * T_TOT + tt[r]]);
                ffma2(oa[h][0], lp[0], p); ffma2(oa[h][1], lp[1], p);
                ffma2(oa[h][2], hp[0], p); ffma2(oa[h][3], hp[1], p);
            }
        }
    }

#pragma unroll
    for (int h = 0; h < 4; h++)
#pragma unroll
        for (int j = 0; j < 4; j++) {
            float2 v = *(float2 *)&oa[h][j];
            v.x += __shfl_xor_sync(~0u, v.x, 16);
            v.y += __shfl_xor_sync(~0u, v.y, 16);
            if (half == 0) {
                int d = hl * 4 + (j & 1) * 2 + (j >> 1) * 64;
                atomicAdd(&accs[h * 128 + d], v.x);
                atomicAdd(&accs[h * 128 + d + 1], v.y);
            }
        }
    __syncthreads();

    for (int i = tid; i < 512; i += 256) {
        int h = i >> 7, d = i & 127;
        g_attn[(size_t)b * 4096 + (kv * 4 + h) * 128 + d] = accs[i] * gsum[h];
    }
}

extern "C" void kernel_launch(void *const *d_in, const int *in_sizes, int n_in,
                              void *d_out, int out_size) {
    const float *x    = (const float *)d_in[0];
    const float *wq   = (const float *)d_in[1];
    const float *wk   = (const float *)d_in[2];
    const float *wv   = (const float *)d_in[3];
    const float *wo   = (const float *)d_in[4];
    const float *kc   = (const float *)d_in[5];
    const float *vc   = (const float *)d_in[6];
    const float *fcos = (const float *)d_in[7];
    const float *fsin = (const float *)d_in[8];
    float *out = (float *)d_out;

    zero_kernel<<<320, 256>>>(out);                        // launch 0
    gemm_qkv_kernel<<<768, 256>>>(x, wq, wk, wv);          // launch 1
    attn_kernel<<<BATCH * NKV, 256>>>(kc, vc, fcos, fsin); // launch 2
    gemm_o_kernel<<<dim3(16, 32), 256>>>(wo, out);         // launch 3 <- ncu
}

// round 12
// speedup vs baseline: 2.1378x; 1.0001x over previous
#include <cuda_runtime.h>
#include <math.h>

typedef unsigned long long ull;

#define BATCH   32
#define DIM     4096
#define NH      32
#define NKV     8
#define HD      128
#define MAXS    2048
#define START_T 2047
#define T_TOT   2048
#define T_HALF  1024
#define RSQRT_HD 0.088388347648318447f

// -------- device scratch --------
__device__ float g_q[BATCH * NH * HD];
__device__ float g_k[BATCH * NKV * HD];
__device__ float g_v[BATCH * NKV * HD];
__device__ float g_attn[BATCH * NH * HD];
// flash partials: index (b*8+kv)*2+sp
__device__ float g_pm[512 * 4];           // local max per head
__device__ float g_ps[512 * 4];           // local sum per head
__device__ float g_po[512 * 4 * HD];      // unnormalized partial out

// -------- packed f32x2 helpers --------
__device__ __forceinline__ void ffma2(ull &acc, ull a, ull b) {
    asm("fma.rn.f32x2 %0, %1, %2, %0;" : "+l"(acc) : "l"(a), "l"(b));
}
__device__ __forceinline__ ull pack2(float w) {
    ull r; unsigned u = __float_as_uint(w);
    asm("mov.b64 %0, {%1, %1};" : "=l"(r) : "r"(u));
    return r;
}
__device__ __forceinline__ void red_add_v4(float *p, float a, float b, float c,
                                           float d) {
    asm volatile("red.global.add.v4.f32 [%0], {%1, %2, %3, %4};"
                 :: "l"(p), "f"(a), "f"(b), "f"(c), "f"(d) : "memory");
}

// -------- zero scratch + output --------
__global__ void zero_kernel(float *__restrict__ out) {
    int i = blockIdx.x * 256 + threadIdx.x;
    for (; i < 327680; i += 81920) {
        if (i < 131072)       g_q[i] = 0.f;
        else if (i < 163840)  g_k[i - 131072] = 0.f;
        else if (i < 196608)  g_v[i - 163840] = 0.f;
        else                  out[i - 196608] = 0.f;
    }
}

// -------- GEMM inner compute: one 4-k block --------
__device__ __forceinline__ void gemm_compute4(const float4 *w,
                                              const float (*xs)[32], int k,
                                              int ty, ull (*acc)[4]) {
#pragma unroll
    for (int kk = 0; kk < 4; kk++) {
        float4 xa = *(const float4 *)&xs[k + kk][ty * 8];
        float4 xb = *(const float4 *)&xs[k + kk][ty * 8 + 4];
        ull xp[4];
        xp[0] = *(const ull *)&xa.x; xp[1] = *(const ull *)&xa.z;
        xp[2] = *(const ull *)&xb.x; xp[3] = *(const ull *)&xb.z;
        const float *wf = (const float *)&w[kk];
#pragma unroll
        for (int c = 0; c < 4; c++) {
            ull wc = pack2(wf[c]);
#pragma unroll
            for (int i = 0; i < 4; i++) ffma2(acc[c][i], xp[i], wc);
        }
    }
}

// -------- GEMM body: Y[32,N] += X[32,4096] @ W[4096,N], KB=128 --------
// 256 threads, CTA tile 256 cols x 32 batches; double-buffered W loads.
__device__ __forceinline__ void gemm_body(const float *__restrict__ X,
                                          const float *__restrict__ W,
                                          float *__restrict__ Y, int N,
                                          int jblock, int kbeg,
                                          float (*xs)[32]) {
    const int tid = threadIdx.x;
    const int tx = tid & 63;
    const int ty = tid >> 6;
    const int j0 = jblock + tx * 4;

    for (int idx = tid; idx < 1024; idx += 256) {
        int bb = idx & 31, c = idx >> 5;
        float4 xv = *(const float4 *)(X + (size_t)bb * DIM + kbeg + 4 * c);
        xs[4 * c + 0][bb] = xv.x; xs[4 * c + 1][bb] = xv.y;
        xs[4 * c + 2][bb] = xv.z; xs[4 * c + 3][bb] = xv.w;
    }
    __syncthreads();

    ull acc[4][4];
#pragma unroll
    for (int c = 0; c < 4; c++)
#pragma unroll
        for (int i = 0; i < 4; i++) acc[c][i] = 0ULL;

    const float *wp = W + (size_t)kbeg * N + j0;
    float4 wA[4], wB[4];
#pragma unroll
    for (int kk = 0; kk < 4; kk++)
        wA[kk] = *(const float4 *)(wp + (size_t)kk * N);

    for (int k = 0; k < 128; k += 8) {
        const float *pB = wp + (size_t)(k + 4) * N;
#pragma unroll
        for (int kk = 0; kk < 4; kk++)
            wB[kk] = *(const float4 *)(pB + (size_t)kk * N);
        gemm_compute4(wA, xs, k, ty, acc);
        if (k + 8 < 128) {
            const float *pA = wp + (size_t)(k + 8) * N;
#pragma unroll
            for (int kk = 0; kk < 4; kk++)
                wA[kk] = *(const float4 *)(pA + (size_t)kk * N);
        }
        gemm_compute4(wB, xs, k + 4, ty, acc);
    }

#pragma unroll
    for (int i = 0; i < 4; i++) {
        int bb = ty * 8 + 2 * i;
        float2 v0 = *(float2 *)&acc[0][i];
        float2 v1 = *(float2 *)&acc[1][i];
        float2 v2 = *(float2 *)&acc[2][i];
        float2 v3 = *(float2 *)&acc[3][i];
        red_add_v4(&Y[(size_t)bb * N + j0], v0.x, v1.x, v2.x, v3.x);
        red_add_v4(&Y[(size_t)(bb + 1) * N + j0], v0.y, v1.y, v2.y, v3.y);
    }
}

// Merged QKV: 768 CTAs. 0-511 wq, 512-639 wk, 640-767 wv
__global__ void __launch_bounds__(256, 3)
gemm_qkv_kernel(const float *__restrict__ X, const float *__restrict__ Wq,
                const float *__restrict__ Wk, const float *__restrict__ Wv) {
    __shared__ float xs[128][32];
    int id = blockIdx.x;
    if (id < 512) {
        gemm_body(X, Wq, g_q, 4096, (id & 15) * 256, (id >> 4) * 128, xs);
    } else {
        int id2 = id - 512;
        const float *W = (id2 & 128) ? Wv : Wk;
        float *Y = (id2 & 128) ? g_v : g_k;
        int id3 = id2 & 127;
        gemm_body(X, W, Y, 1024, (id3 & 3) * 256, (id3 >> 2) * 128, xs);
    }
}

__global__ void __launch_bounds__(256, 3)
gemm_o_kernel(const float *__restrict__ W, float *__restrict__ out) {
    __shared__ float xs[128][32];
    gemm_body(g_attn, W, out, 4096, blockIdx.x * 256, blockIdx.y * 128, xs);
}

// -------- Attention, 2-way T-split: block per (b, kv, sp) --------
__global__ void __launch_bounds__(256)
attn_kernel(const float *__restrict__ kc, const float *__restrict__ vc,
            const float *__restrict__ fcos, const float *__restrict__ fsin) {
    const int b  = blockIdx.x >> 4;
    const int kv = (blockIdx.x >> 1) & 7;
    const int sp = blockIdx.x & 1;
    const int tbase = sp * T_HALF;
    const int tid = threadIdx.x;
    const int lane = tid & 31;
    const int wid = tid >> 5;
    const int hl = lane & 15;
    const int half = lane >> 4;

    __shared__ float qs[512];
    __shared__ float sc[4 * T_HALF];
    __shared__ float accs[512];
    __shared__ float red[32];
    __shared__ float gmax[4], gsum[4];

    // RoPE q into smem (one pair per thread), pre-scaled
    {
        int h = tid >> 6, i = tid & 63;
        float c = fcos[i], s = fsin[i];
        const float *qb = g_q + (size_t)b * 4096 + kv * 512 + h * 128 + 2 * i;
        float xr = qb[0], xi = qb[1];
        qs[h * 128 + 2 * i]     = (xr * c - xi * s) * RSQRT_HD;
        qs[h * 128 + 2 * i + 1] = (xr * s + xi * c) * RSQRT_HD;
    }
    for (int i = tid; i < 512; i += 256) accs[i] = 0.f;
    // RoPE new K row in place: only the sp=1 CTA owns/reads t=2047
    if (sp == 1 && tid < 64) {
        int i = tid;
        float c = fcos[i], s = fsin[i];
        float *kb2 = g_k + (size_t)(b * NKV + kv) * HD + 2 * i;
        float xr = kb2[0], xi = kb2[1];
        kb2[0] = xr * c - xi * s;
        kb2[1] = xr * s + xi * c;
    }
    __syncthreads();

    ull qp[4][4];
#pragma unroll
    for (int h = 0; h < 4; h++) {
        const ull *qa = (const ull *)&qs[h * 128 + hl * 4];
        const ull *qb = (const ull *)&qs[h * 128 + hl * 4 + 64];
        qp[h][0] = qa[0]; qp[h][1] = qa[1];
        qp[h][2] = qb[0]; qp[h][3] = qb[1];
    }

    const float *kbase = kc + ((size_t)b * MAXS * NKV + kv) * HD;
    const float *knew  = g_k + (size_t)(b * NKV + kv) * HD;

    // Phase 1: scores over [tbase, tbase+1024)
    for (int tb = tbase + wid * 8; tb < tbase + T_HALF; tb += 64) {
        int t0 = tb + half, t1 = tb + 2 + half, t2 = tb + 4 + half, t3 = tb + 6 + half;
        const float *k0p = (t0 == START_T) ? knew : kbase + (size_t)t0 * (NKV * HD);
        const float *k1p = (t1 == START_T) ? knew : kbase + (size_t)t1 * (NKV * HD);
        const float *k2p = (t2 == START_T) ? knew : kbase + (size_t)t2 * (NKV * HD);
        const float *k3p = (t3 == START_T) ? knew : kbase + (size_t)t3 * (NKV * HD);
        float4 lo[4], hi[4];
        lo[0] = *(const float4 *)(k0p + hl * 4); hi[0] = *(const float4 *)(k0p + hl * 4 + 64);
        lo[1] = *(const float4 *)(k1p + hl * 4); hi[1] = *(const float4 *)(k1p + hl * 4 + 64);
        lo[2] = *(const float4 *)(k2p + hl * 4); hi[2] = *(const float4 *)(k2p + hl * 4 + 64);
        lo[3] = *(const float4 *)(k3p + hl * 4); hi[3] = *(const float4 *)(k3p + hl * 4 + 64);

        float f[4][4];
#pragma unroll
        for (int r = 0; r < 4; r++) {
            const ull *lp = (const ull *)&lo[r];
            const ull *hp = (const ull *)&hi[r];
#pragma unroll
            for (int h = 0; h < 4; h++) {
                ull s = 0ULL;
                ffma2(s, lp[0], qp[h][0]); ffma2(s, lp[1], qp[h][1]);
                ffma2(s, hp[0], qp[h][2]); ffma2(s, hp[1], qp[h][3]);
                float2 v = *(float2 *)&s;
                f[h][r] = v.x + v.y;
            }
        }
#pragma unroll
        for (int off = 8; off; off >>= 1)
#pragma unroll
            for (int h = 0; h < 4; h++) {
                f[h][0] += __shfl_xor_sync(~0u, f[h][0], off);
                f[h][1] += __shfl_xor_sync(~0u, f[h][1], off);
                f[h][2] += __shfl_xor_sync(~0u, f[h][2], off);
                f[h][3] += __shfl_xor_sync(~0u, f[h][3], off);
            }
        if (hl == 0) {
#pragma unroll
            for (int h = 0; h < 4; h++) {
                sc[h * T_HALF + t0 - tbase] = f[h][0];
                sc[h * T_HALF + t1 - tbase] = f[h][1];
                sc[h * T_HALF + t2 - tbase] = f[h][2];
                sc[h * T_HALF + t3 - tbase] = f[h][3];
            }
        }
    }
    __syncthreads();

    // Phase 2: local softmax stats (deferred normalization)
    float m0 = -1e30f, m1 = -1e30f, m2 = -1e30f, m3 = -1e30f;
    for (int t = tid; t < T_HALF; t += 256) {
        m0 = fmaxf(m0, sc[t]);
        m1 = fmaxf(m1, sc[T_HALF + t]);
        m2 = fmaxf(m2, sc[2 * T_HALF + t]);
        m3 = fmaxf(m3, sc[3 * T_HALF + t]);
    }
#pragma unroll
    for (int off = 16; off; off >>= 1) {
        m0 = fmaxf(m0, __shfl_xor_sync(~0u, m0, off));
        m1 = fmaxf(m1, __shfl_xor_sync(~0u, m1, off));
        m2 = fmaxf(m2, __shfl_xor_sync(~0u, m2, off));
        m3 = fmaxf(m3, __shfl_xor_sync(~0u, m3, off));
    }
    if (lane == 0) { red[wid * 4 + 0] = m0; red[wid * 4 + 1] = m1;
                     red[wid * 4 + 2] = m2; red[wid * 4 + 3] = m3; }
    __syncthreads();
    if (tid < 4) {
        float m = red[tid];
#pragma unroll
        for (int w = 1; w < 8; w++) m = fmaxf(m, red[w * 4 + tid]);
        gmax[tid] = m;
    }
    __syncthreads();
    m0 = gmax[0]; m1 = gmax[1]; m2 = gmax[2]; m3 = gmax[3];

    float sm0 = 0.f, sm1 = 0.f, sm2 = 0.f, sm3 = 0.f;
    for (int t = tid; t < T_HALF; t += 256) {
        float e0 = __expf(sc[t] - m0);                sc[t] = e0;                sm0 += e0;
        float e1 = __expf(sc[T_HALF + t] - m1);       sc[T_HALF + t] = e1;       sm1 += e1;
        float e2 = __expf(sc[2 * T_HALF + t] - m2);   sc[2 * T_HALF + t] = e2;   sm2 += e2;
        float e3 = __expf(sc[3 * T_HALF + t] - m3);   sc[3 * T_HALF + t] = e3;   sm3 += e3;
    }
#pragma unroll
    for (int off = 16; off; off >>= 1) {
        sm0 += __shfl_xor_sync(~0u, sm0, off);
        sm1 += __shfl_xor_sync(~0u, sm1, off);
        sm2 += __shfl_xor_sync(~0u, sm2, off);
        sm3 += __shfl_xor_sync(~0u, sm3, off);
    }
    __syncthreads();
    if (lane == 0) { red[wid * 4 + 0] = sm0; red[wid * 4 + 1] = sm1;
                     red[wid * 4 + 2] = sm2; red[wid * 4 + 3] = sm3; }
    __syncthreads();
    if (tid < 4) {
        float s = 0.f;
#pragma unroll
        for (int w = 0; w < 8; w++) s += red[w * 4 + tid];
        gsum[tid] = s;     // raw sum; combine normalizes
    }
    __syncthreads();

    // Phase 3: P @ V over local half
    ull oa[4][4];
#pragma unroll
    for (int h = 0; h < 4; h++)
#pragma unroll
        for (int j = 0; j < 4; j++) oa[h][j] = 0ULL;

    const float *vbase = vc + ((size_t)b * MAXS * NKV + kv) * HD;
    const float *vnew  = g_v + (size_t)(b * NKV + kv) * HD;
    for (int tb = tbase + wid * 8; tb < tbase + T_HALF; tb += 64) {
        int t0 = tb + half, t1 = tb + 2 + half, t2 = tb + 4 + half, t3 = tb + 6 + half;
        const float *v0p = (t0 == START_T) ? vnew : vbase + (size_t)t0 * (NKV * HD);
        const float *v1p = (t1 == START_T) ? vnew : vbase + (size_t)t1 * (NKV * HD);
        const float *v2p = (t2 == START_T) ? vnew : vbase + (size_t)t2 * (NKV * HD);
        const float *v3p = (t3 == START_T) ? vnew : vbase + (size_t)t3 * (NKV * HD);
        float4 lo[4], hi[4];
        lo[0] = *(const float4 *)(v0p + hl * 4); hi[0] = *(const float4 *)(v0p + hl * 4 + 64);
        lo[1] = *(const float4 *)(v1p + hl * 4); hi[1] = *(const float4 *)(v1p + hl * 4 + 64);
        lo[2] = *(const float4 *)(v2p + hl * 4); hi[2] = *(const float4 *)(v2p + hl * 4 + 64);
        lo[3] = *(const float4 *)(v3p + hl * 4); hi[3] = *(const float4 *)(v3p + hl * 4 + 64);
        int tt[4] = {t0 - tbase, t1 - tbase, t2 - tbase, t3 - tbase};
#pragma unroll
        for (int r = 0; r < 4; r++) {
            const ull *lp = (const ull *)&lo[r];
            const ull *hp = (const ull *)&hi[r];
#pragma unroll
            for (int h = 0; h < 4; h++) {
                ull p = pack2(sc[h * T_HALF + tt[r]]);
                ffma2(oa[h][0], lp[0], p); ffma2(oa[h][1], lp[1], p);
                ffma2(oa[h][2], hp[0], p); ffma2(oa[h][3], hp[1], p);
            }
        }
    }

#pragma unroll
    for (int h = 0; h < 4; h++)
#pragma unroll
        for (int j = 0; j < 4; j++) {
            float2 v = *(float2 *)&oa[h][j];
            v.x += __shfl_xor_sync(~0u, v.x, 16);
            v.y += __shfl_xor_sync(~0u, v.y, 16);
            if (half == 0) {
                int d = hl * 4 + (j & 1) * 2 + (j >> 1) * 64;
                atomicAdd(&accs[h * 128 + d], v.x);
                atomicAdd(&accs[h * 128 + d + 1], v.y);
            }
        }
    __syncthreads();

    // write partials
    const int pidx = ((b * NKV + kv) * 2 + sp) * 4;
    if (tid < 4) {
        g_pm[pidx + tid] = gmax[tid];
        g_ps[pidx + tid] = gsum[tid];
    }
    for (int i = tid; i < 512; i += 256) {
        int h = i >> 7, d = i & 127;
        g_po[(size_t)(pidx + h) * HD + d] = accs[i];
    }
}

// -------- combine the two T-halves --------
__global__ void __launch_bounds__(256)
combine_kernel() {
    int bk = blockIdx.x;              // (b*8+kv)
    int tid = threadIdx.x;
    int b = bk >> 3, kv = bk & 7;
    int p0 = bk * 2 * 4, p1 = (bk * 2 + 1) * 4;
    for (int i = tid; i < 512; i += 256) {
        int h = i >> 7, d = i & 127;
        float m0 = g_pm[p0 + h], m1 = g_pm[p1 + h];
        float s0 = g_ps[p0 + h], s1 = g_ps[p1 + h];
        float M = fmaxf(m0, m1);
        float w0 = __expf(m0 - M), w1 = __expf(m1 - M);
        float o0 = g_po[(size_t)(p0 + h) * HD + d];
        float o1 = g_po[(size_t)(p1 + h) * HD + d];
        float r = (w0 * o0 + w1 * o1) / (w0 * s0 + w1 * s1);
        g_attn[(size_t)b * 4096 + (kv * 4 + h) * 128 + d] = r;
    }
}

extern "C" void kernel_launch(void *const *d_in, const int *in_sizes, int n_in,
                              void *d_out, int out_size) {
    const float *x    = (const float *)d_in[0];
    const float *wq   = (const float *)d_in[1];
    const float *wk   = (const float *)d_in[2];
    const float *wv   = (const float *)d_in[3];
    const float *wo   = (const float *)d_in[4];
    const float *kc   = (const float *)d_in[5];
    const float *vc   = (const float *)d_in[6];
    const float *fcos = (const float *)d_in[7];
    const float *fsin = (const float *)d_in[8];
    float *out = (float *)d_out;

    zero_kernel<<<320, 256>>>(out);                        // 0
    gemm_qkv_kernel<<<768, 256>>>(x, wq, wk, wv);          // 1
    attn_kernel<<<512, 256>>>(kc, vc, fcos, fsin);         // 2
    combine_kernel<<<256, 256>>>();                        // 3
    gemm_o_kernel<<<dim3(16, 32), 256>>>(wo, out);         // 4
}